// round 1
// baseline (speedup 1.0000x reference)
#include <cuda_runtime.h>
#include <cstdint>
#include <cstddef>

#define B_ 8
#define Q_ 32
#define T_ 128   // LE
#define D_ 512
#define P_ 32
#define A_ 128

// Scratch (no cudaMalloc allowed): ws (128KB), uh (16.8MB), attn (4MB)
__device__ float g_ws[B_ * P_ * A_];
__device__ float g_uh[(size_t)B_ * Q_ * T_ * A_];
__device__ float g_attn[(size_t)B_ * Q_ * P_ * T_];

// ---------------- helpers ----------------
__device__ __forceinline__ float fast_tanh(float x) {
    float y; asm("tanh.approx.f32 %0, %1;" : "=f"(y) : "f"(x)); return y;
}
__device__ __forceinline__ unsigned long long pack2(float lo, float hi) {
    unsigned long long r; asm("mov.b64 %0, {%1, %2};" : "=l"(r) : "f"(lo), "f"(hi)); return r;
}
__device__ __forceinline__ void unpack2(unsigned long long v, float& lo, float& hi) {
    asm("mov.b64 {%0, %1}, %2;" : "=f"(lo), "=f"(hi) : "l"(v));
}
__device__ __forceinline__ unsigned long long ffma2(unsigned long long a,
                                                    unsigned long long b,
                                                    unsigned long long c) {
    unsigned long long d;
    asm("fma.rn.f32x2 %0, %1, %2, %3;" : "=l"(d) : "l"(a), "l"(b), "l"(c));
    return d;
}

// ---------------- kernel 1: ws[b,p,a] = s_j[b,p,:] . Ws_w[a,:] + Ws_b[a] ----------------
__global__ void k_ws(const float* __restrict__ s_j,
                     const float* __restrict__ Ws_w,
                     const float* __restrict__ Ws_b) {
    __shared__ float srow[D_];
    int bp = blockIdx.x;       // b*P + p  (256 blocks)
    int a  = threadIdx.x;      // 0..127
    ((float4*)srow)[a] = ((const float4*)(s_j + (size_t)bp * D_))[a];
    __syncthreads();
    const float* w = Ws_w + (size_t)a * D_;
    float acc = 0.f;
#pragma unroll 8
    for (int d = 0; d < D_; d++) acc = fmaf(srow[d], w[d], acc);
    g_ws[bp * A_ + a] = acc + Ws_b[a];
}

// ---------------- kernel 2: uh[m, a] = exp_tokens[m,:] . U_w[a,:] ----------------
// M = B*Q*T = 32768, N = A = 128, K = D = 512. Tiles BM=128, BN=128, BK=32.
__global__ __launch_bounds__(256) void k_uh(const float* __restrict__ tok,
                                            const float* __restrict__ Uw) {
    __shared__ unsigned long long As2[32][128];  // A values pre-duplicated into f32x2 pairs (32KB)
    __shared__ float Us[32][128];                // U tile, k-major (16KB)
    int tid = threadIdx.x;
    int tx = tid & 15, ty = tid >> 4;            // tx: a-groups, ty: m-groups
    int m0 = blockIdx.x * 128;

    unsigned long long acc[8][4];
#pragma unroll
    for (int i = 0; i < 8; i++)
#pragma unroll
        for (int j = 0; j < 4; j++) acc[i][j] = 0ull;

    for (int k0 = 0; k0 < D_; k0 += 32) {
#pragma unroll
        for (int s = 0; s < 4; s++) {
            int id = s * 256 + tid;              // 1024 float4 of the A tile
            int r = id >> 3, c4 = id & 7;
            float4 v = *(const float4*)(tok + (size_t)(m0 + r) * D_ + k0 + c4 * 4);
            As2[c4 * 4 + 0][r] = pack2(v.x, v.x);
            As2[c4 * 4 + 1][r] = pack2(v.y, v.y);
            As2[c4 * 4 + 2][r] = pack2(v.z, v.z);
            As2[c4 * 4 + 3][r] = pack2(v.w, v.w);
        }
#pragma unroll
        for (int s = 0; s < 4; s++) {
            int id = s * 256 + tid;
            int r = id >> 3, c4 = id & 7;
            float4 v = *(const float4*)(Uw + (size_t)r * D_ + k0 + c4 * 4);
            Us[c4 * 4 + 0][r] = v.x;
            Us[c4 * 4 + 1][r] = v.y;
            Us[c4 * 4 + 2][r] = v.z;
            Us[c4 * 4 + 3][r] = v.w;
        }
        __syncthreads();
#pragma unroll
        for (int kk = 0; kk < 32; kk++) {
            const unsigned long long* urow = (const unsigned long long*)&Us[kk][0];
            ulonglong2 u0 = *(const ulonglong2*)(urow + tx * 4);
            ulonglong2 u1 = *(const ulonglong2*)(urow + tx * 4 + 2);
            unsigned long long fa[4] = {u0.x, u0.y, u1.x, u1.y};
#pragma unroll
            for (int i = 0; i < 8; i++) {
                unsigned long long fm = As2[kk][ty * 8 + i];
#pragma unroll
                for (int j = 0; j < 4; j++) acc[i][j] = ffma2(fm, fa[j], acc[i][j]);
            }
        }
        __syncthreads();
    }
#pragma unroll
    for (int i = 0; i < 8; i++) {
        float o[8];
#pragma unroll
        for (int j = 0; j < 4; j++) unpack2(acc[i][j], o[2 * j], o[2 * j + 1]);
        float* dst = g_uh + (size_t)(m0 + ty * 8 + i) * A_ + tx * 8;
        *(float4*)dst       = make_float4(o[0], o[1], o[2], o[3]);
        *(float4*)(dst + 4) = make_float4(o[4], o[5], o[6], o[7]);
    }
}

// ---------------- kernel 3: scores + softmax over joint (q,t) per (b,p) ----------------
__global__ __launch_bounds__(256) void k_attn(const int* __restrict__ exp_mask,
                                              const float* __restrict__ v_w) {
    __shared__ float ebuf[Q_ * T_];  // 4096 scores
    __shared__ float red[8];
    int bp = blockIdx.x;             // 256 blocks
    int b = bp >> 5, p = bp & 31;
    int tid = threadIdx.x;
    int lane = tid & 31, w = tid >> 5;

    float v4[4], ws4[4];
#pragma unroll
    for (int i = 0; i < 4; i++) {
        v4[i]  = v_w[lane + 32 * i];
        ws4[i] = g_ws[bp * A_ + lane + 32 * i];
    }
    const float* uhb = g_uh + (size_t)b * Q_ * T_ * A_;
    const int* mk = exp_mask + b * Q_ * T_;

    // each warp: one (q,t) element at a time; 128-dot with tanh, warp-reduced
    for (int e = w; e < Q_ * T_; e += 8) {
        const float* u = uhb + (size_t)e * A_;
        float s = 0.f;
#pragma unroll
        for (int i = 0; i < 4; i++)
            s = fmaf(v4[i], fast_tanh(u[lane + 32 * i] + ws4[i]), s);
#pragma unroll
        for (int o = 16; o > 0; o >>= 1) s += __shfl_xor_sync(0xffffffffu, s, o);
        if (lane == 0) {
            if (mk[e] == 0) s = -1e9f;
            ebuf[e] = s;
        }
    }
    __syncthreads();

    // block softmax over 4096
    float mx = -3.4e38f;
    int e0 = tid * 16;
#pragma unroll
    for (int j = 0; j < 16; j++) mx = fmaxf(mx, ebuf[e0 + j]);
#pragma unroll
    for (int o = 16; o > 0; o >>= 1) mx = fmaxf(mx, __shfl_xor_sync(0xffffffffu, mx, o));
    if (lane == 0) red[w] = mx;
    __syncthreads();
    mx = red[0];
#pragma unroll
    for (int i = 1; i < 8; i++) mx = fmaxf(mx, red[i]);

    float sm = 0.f;
#pragma unroll
    for (int j = 0; j < 16; j++) {
        float ex = __expf(ebuf[e0 + j] - mx);
        ebuf[e0 + j] = ex;
        sm += ex;
    }
#pragma unroll
    for (int o = 16; o > 0; o >>= 1) sm += __shfl_xor_sync(0xffffffffu, sm, o);
    __syncthreads();               // all reads of red(max) done
    if (lane == 0) red[w] = sm;
    __syncthreads();
    sm = 0.f;
#pragma unroll
    for (int i = 0; i < 8; i++) sm += red[i];
    float inv = 1.0f / sm;

    // write attn[b,q,p,t]; thread's 16 elems stay within one q
    int q = e0 >> 7, t0 = e0 & 127;
    float* dst = g_attn + (((size_t)(b * Q_ + q)) * P_ + p) * T_ + t0;
#pragma unroll
    for (int j = 0; j < 16; j++) dst[j] = ebuf[e0 + j] * inv;
}

// ---------------- kernel 4: out[b,q,p,d] = rmask[b,p] * sum_t attn * tok ----------------
// Per (b,q): C(32 x 512) = A(32 x 128) * B(128 x 512)
__global__ __launch_bounds__(256) void k_out(const float* __restrict__ tok,
                                             const int* __restrict__ req_mask,
                                             float* __restrict__ out) {
    __shared__ float attn_s[P_][T_];  // 16KB
    __shared__ float tok_s[16][D_];   // 32KB
    int bq = blockIdx.x;              // 256 blocks
    int b = bq >> 5;
    int tid = threadIdx.x;
    int tx = tid & 63, ty = tid >> 6; // tx: d-groups (64), ty: p-groups (4)

    {
        const float4* src = (const float4*)(g_attn + (size_t)bq * P_ * T_);
        float4* dst = (float4*)&attn_s[0][0];
#pragma unroll
        for (int s = 0; s < 4; s++) dst[s * 256 + tid] = src[s * 256 + tid];
    }

    unsigned long long acc[8][4];
#pragma unroll
    for (int i = 0; i < 8; i++)
#pragma unroll
        for (int j = 0; j < 4; j++) acc[i][j] = 0ull;

    const float* tb = tok + (size_t)bq * T_ * D_;
    for (int k0 = 0; k0 < T_; k0 += 16) {
        __syncthreads();              // also covers attn_s fill on first iter
#pragma unroll
        for (int s = 0; s < 8; s++) {
            int id = s * 256 + tid;   // 2048 float4 of tok chunk
            int r = id >> 7, c4 = id & 127;
            *(float4*)&tok_s[r][c4 * 4] =
                *(const float4*)(tb + (size_t)(k0 + r) * D_ + c4 * 4);
        }
        __syncthreads();
#pragma unroll
        for (int kk = 0; kk < 16; kk++) {
            const unsigned long long* trow = (const unsigned long long*)&tok_s[kk][0];
            ulonglong2 t0 = *(const ulonglong2*)(trow + tx * 4);
            ulonglong2 t1 = *(const ulonglong2*)(trow + tx * 4 + 2);
            unsigned long long ft[4] = {t0.x, t0.y, t1.x, t1.y};
#pragma unroll
            for (int i = 0; i < 8; i++) {
                float am = attn_s[ty * 8 + i][k0 + kk];
                unsigned long long fm = pack2(am, am);
#pragma unroll
                for (int j = 0; j < 4; j++) acc[i][j] = ffma2(fm, ft[j], acc[i][j]);
            }
        }
    }

#pragma unroll
    for (int i = 0; i < 8; i++) {
        int pp = ty * 8 + i;
        float rm = (float)req_mask[b * P_ + pp];
        float o[8];
#pragma unroll
        for (int j = 0; j < 4; j++) unpack2(acc[i][j], o[2 * j], o[2 * j + 1]);
#pragma unroll
        for (int j = 0; j < 8; j++) o[j] *= rm;
        float* dst = out + ((size_t)bq * P_ + pp) * D_ + tx * 8;
        *(float4*)dst       = make_float4(o[0], o[1], o[2], o[3]);
        *(float4*)(dst + 4) = make_float4(o[4], o[5], o[6], o[7]);
    }
}

// ---------------- launch ----------------
extern "C" void kernel_launch(void* const* d_in, const int* in_sizes, int n_in,
                              void* d_out, int out_size) {
    const float* exp_tokens = (const float*)d_in[0];  // (B,Q,LE,D) f32
    const int*   exp_mask   = (const int*)  d_in[1];  // (B,Q,LE) i32
    const float* s_j        = (const float*)d_in[2];  // (B,P,D) f32
    const int*   req_mask   = (const int*)  d_in[3];  // (B,P) i32
    const float* Ws_w       = (const float*)d_in[4];  // (A,D)
    const float* Ws_b       = (const float*)d_in[5];  // (A,)
    const float* U_w        = (const float*)d_in[6];  // (A,D)
    const float* v_w        = (const float*)d_in[7];  // (1,A)
    float* out = (float*)d_out;                       // (B,Q,P,D) f32

    k_ws  <<<B_ * P_, 128>>>(s_j, Ws_w, Ws_b);
    k_uh  <<<(B_ * Q_ * T_) / 128, 256>>>(exp_tokens, U_w);
    k_attn<<<B_ * P_, 256>>>(exp_mask, v_w);
    k_out <<<B_ * Q_, 256>>>(exp_tokens, req_mask, out);
}

// round 3
// speedup vs baseline: 1.5871x; 1.5871x over previous
#include <cuda_runtime.h>
#include <cstdint>
#include <cstddef>

#define B_ 8
#define Q_ 32
#define T_ 128   // LE
#define D_ 512
#define P_ 32
#define A_ 128

// Scratch: ws (128KB), e/attn (4MB, layout [b][p][q][t])
__device__ float g_ws[B_ * P_ * A_];
__device__ float g_e[(size_t)B_ * P_ * Q_ * T_];

// ---------------- helpers ----------------
__device__ __forceinline__ float fast_tanh(float x) {
    float y; asm("tanh.approx.f32 %0, %1;" : "=f"(y) : "f"(x)); return y;
}
__device__ __forceinline__ unsigned long long pack2(float lo, float hi) {
    unsigned long long r; asm("mov.b64 %0, {%1, %2};" : "=l"(r) : "f"(lo), "f"(hi)); return r;
}
__device__ __forceinline__ void unpack2(unsigned long long v, float& lo, float& hi) {
    asm("mov.b64 {%0, %1}, %2;" : "=f"(lo), "=f"(hi) : "l"(v));
}
__device__ __forceinline__ unsigned long long ffma2(unsigned long long a,
                                                    unsigned long long b,
                                                    unsigned long long c) {
    unsigned long long d;
    asm("fma.rn.f32x2 %0, %1, %2, %3;" : "=l"(d) : "l"(a), "l"(b), "l"(c));
    return d;
}

// ---------------- kernel 1: ws[b,p,a] = s_j[b,p,:] . Ws_w[a,:] + Ws_b[a] ----------------
__global__ void k_ws(const float* __restrict__ s_j,
                     const float* __restrict__ Ws_w,
                     const float* __restrict__ Ws_b) {
    __shared__ float srow[D_];
    int bp = blockIdx.x;
    int a  = threadIdx.x;
    ((float4*)srow)[a] = ((const float4*)(s_j + (size_t)bp * D_))[a];
    __syncthreads();
    const float* w = Ws_w + (size_t)a * D_;
    float acc = 0.f;
#pragma unroll 8
    for (int d = 0; d < D_; d++) acc = fmaf(srow[d], w[d], acc);
    g_ws[bp * A_ + a] = acc + Ws_b[a];
}

// ---------------- fused kernel: uh GEMM (128x128x512) + scores per (b,q) ----------------
// Dynamic smem layout (bytes):
//   [0, 32768)       phase1: As2  (ull[32][128])     | phase2: uh_s (float[128][128], [0,65536))
//   [32768, 49152)   phase1: Us   (float[32][128])   |
//   [65536, 81920)   ws_t  (float[128][32], [a][p])
//   [81920, 82432)   v_s   (float[128])
//   [82432, 82944)   mask_s(int[128])
#define SMEM_FUSED 82944

__global__ __launch_bounds__(256, 2) void k_uh_score(const float* __restrict__ tok,
                                                     const float* __restrict__ Uw,
                                                     const int* __restrict__ exp_mask,
                                                     const float* __restrict__ v_w) {
    extern __shared__ char smem[];
    unsigned long long* As2 = (unsigned long long*)smem;          // [32][128]
    float* Us   = (float*)(smem + 32768);                         // [32][128]
    float* uh_s = (float*)smem;                                   // [128][128]
    float* ws_t = (float*)(smem + 65536);                         // [a][p]
    float* v_s  = (float*)(smem + 81920);
    int*   mask_s = (int*)(smem + 82432);

    int tid = threadIdx.x;
    int bq = blockIdx.x;                 // b*Q + q
    int b = bq >> 5, q = bq & 31;
    int m0 = bq * 128;                   // row base in flattened (b,q,t)

    // preload ws (transposed), v, mask — these regions don't alias phase-1 tiles
#pragma unroll
    for (int s = 0; s < 16; s++) {
        int it = s * 256 + tid;          // 0..4095
        int pp = it >> 7, aa = it & 127;
        ws_t[aa * 32 + pp] = g_ws[b * (P_ * A_) + it];
    }
    if (tid < 128) {
        v_s[tid] = v_w[tid];
        mask_s[tid] = exp_mask[(b * Q_ + q) * T_ + tid];
    }

    // ---- phase 1: uh tile GEMM ----
    int tx = tid & 15, ty = tid >> 4;    // tx: a-groups (8 wide), ty: m-groups (8 tall)
    unsigned long long acc[8][4];
#pragma unroll
    for (int i = 0; i < 8; i++)
#pragma unroll
        for (int j = 0; j < 4; j++) acc[i][j] = 0ull;

    for (int k0 = 0; k0 < D_; k0 += 32) {
        __syncthreads();
#pragma unroll
        for (int s = 0; s < 4; s++) {
            int id = s * 256 + tid;
            int r = id >> 3, c4 = id & 7;
            float4 v = *(const float4*)(tok + (size_t)(m0 + r) * D_ + k0 + c4 * 4);
            As2[(c4 * 4 + 0) * 128 + r] = pack2(v.x, v.x);
            As2[(c4 * 4 + 1) * 128 + r] = pack2(v.y, v.y);
            As2[(c4 * 4 + 2) * 128 + r] = pack2(v.z, v.z);
            As2[(c4 * 4 + 3) * 128 + r] = pack2(v.w, v.w);
        }
#pragma unroll
        for (int s = 0; s < 4; s++) {
            int id = s * 256 + tid;
            int r = id >> 3, c4 = id & 7;
            float4 v = *(const float4*)(Uw + (size_t)r * D_ + k0 + c4 * 4);
            Us[(c4 * 4 + 0) * 128 + r] = v.x;
            Us[(c4 * 4 + 1) * 128 + r] = v.y;
            Us[(c4 * 4 + 2) * 128 + r] = v.z;
            Us[(c4 * 4 + 3) * 128 + r] = v.w;
        }
        __syncthreads();
#pragma unroll
        for (int kk = 0; kk < 32; kk++) {
            const unsigned long long* urow = (const unsigned long long*)(Us + kk * 128);
            ulonglong2 u0 = *(const ulonglong2*)(urow + tx * 4);
            ulonglong2 u1 = *(const ulonglong2*)(urow + tx * 4 + 2);
            unsigned long long fa[4] = {u0.x, u0.y, u1.x, u1.y};
#pragma unroll
            for (int i = 0; i < 8; i++) {
                unsigned long long fm = As2[kk * 128 + ty * 8 + i];
#pragma unroll
                for (int j = 0; j < 4; j++) acc[i][j] = ffma2(fm, fa[j], acc[i][j]);
            }
        }
    }
    __syncthreads();   // all reads of phase-1 tiles finished

    // write uh tile to smem (reusing tile region)
#pragma unroll
    for (int i = 0; i < 8; i++) {
        float o[8];
#pragma unroll
        for (int j = 0; j < 4; j++) unpack2(acc[i][j], o[2 * j], o[2 * j + 1]);
        float* dst = uh_s + (ty * 8 + i) * 128 + tx * 8;
        *(float4*)dst       = make_float4(o[0], o[1], o[2], o[3]);
        *(float4*)(dst + 4) = make_float4(o[4], o[5], o[6], o[7]);
    }
    __syncthreads();

    // ---- phase 2: scores for all 32 p, 128 t ----
    int p = tid & 31, rg = tid >> 5;     // 8 row-groups of 16 rows
    float* edst = g_e + ((size_t)(b * P_ + p) * Q_ + q) * T_;
#pragma unroll
    for (int r = 0; r < 16; r++) {
        int row = rg * 16 + r;           // = t
        const float* u = uh_s + row * 128;
        float s = 0.f;
#pragma unroll 16
        for (int a = 0; a < 128; a++)
            s = fmaf(v_s[a], fast_tanh(u[a] + ws_t[a * 32 + p]), s);
        if (mask_s[row] == 0) s = -1e9f;
        edst[row] = s;
    }
}

// ---------------- softmax over 4096 contiguous elems per (b,p), in place ----------------
__global__ __launch_bounds__(256) void k_softmax() {
    __shared__ float red[8];
    int bp = blockIdx.x;
    int tid = threadIdx.x;
    int lane = tid & 31, w = tid >> 5;
    float* e = g_e + (size_t)bp * (Q_ * T_);

    float buf[16];
    float4* ep = (float4*)(e + tid * 16);
#pragma unroll
    for (int j = 0; j < 4; j++) {
        float4 v = ep[j];
        buf[4 * j + 0] = v.x; buf[4 * j + 1] = v.y;
        buf[4 * j + 2] = v.z; buf[4 * j + 3] = v.w;
    }
    float mx = -3.4e38f;
#pragma unroll
    for (int j = 0; j < 16; j++) mx = fmaxf(mx, buf[j]);
#pragma unroll
    for (int o = 16; o > 0; o >>= 1) mx = fmaxf(mx, __shfl_xor_sync(0xffffffffu, mx, o));
    if (lane == 0) red[w] = mx;
    __syncthreads();
    mx = red[0];
#pragma unroll
    for (int i = 1; i < 8; i++) mx = fmaxf(mx, red[i]);

    float sm = 0.f;
#pragma unroll
    for (int j = 0; j < 16; j++) {
        float ex = __expf(buf[j] - mx);
        buf[j] = ex;
        sm += ex;
    }
#pragma unroll
    for (int o = 16; o > 0; o >>= 1) sm += __shfl_xor_sync(0xffffffffu, sm, o);
    __syncthreads();
    if (lane == 0) red[w] = sm;
    __syncthreads();
    sm = 0.f;
#pragma unroll
    for (int i = 0; i < 8; i++) sm += red[i];
    float inv = 1.0f / sm;

#pragma unroll
    for (int j = 0; j < 4; j++)
        ep[j] = make_float4(buf[4 * j + 0] * inv, buf[4 * j + 1] * inv,
                            buf[4 * j + 2] * inv, buf[4 * j + 3] * inv);
}

// ---------------- k_out: out[b,q,p,d] = rmask[b,p] * sum_t attn[b,p,q,t] * tok[b,q,t,d] ----------------
__global__ __launch_bounds__(256, 2) void k_out(const float* __restrict__ tok,
                                                const int* __restrict__ req_mask,
                                                float* __restrict__ out) {
    __shared__ float attn_s[P_][T_];  // 16KB
    __shared__ float tok_s[16][D_];   // 32KB
    int bq = blockIdx.x;
    int b = bq >> 5, q = bq & 31;
    int tid = threadIdx.x;
    int tx = tid & 63, ty = tid >> 6;

    {
        // attn[b,p,q,t]: per p, 128 contiguous floats
#pragma unroll
        for (int s = 0; s < 4; s++) {
            int id = s * 256 + tid;       // 1024 float4
            int pp = id >> 5, c = id & 31;
            const float* src = g_e + ((size_t)(b * P_ + pp) * Q_ + q) * T_ + c * 4;
            *(float4*)&attn_s[pp][c * 4] = *(const float4*)src;
        }
    }

    unsigned long long acc[8][4];
#pragma unroll
    for (int i = 0; i < 8; i++)
#pragma unroll
        for (int j = 0; j < 4; j++) acc[i][j] = 0ull;

    const float* tb = tok + (size_t)bq * T_ * D_;
    for (int k0 = 0; k0 < T_; k0 += 16) {
        __syncthreads();
#pragma unroll
        for (int s = 0; s < 8; s++) {
            int id = s * 256 + tid;
            int r = id >> 7, c4 = id & 127;
            *(float4*)&tok_s[r][c4 * 4] =
                *(const float4*)(tb + (size_t)(k0 + r) * D_ + c4 * 4);
        }
        __syncthreads();
#pragma unroll
        for (int kk = 0; kk < 16; kk++) {
            const unsigned long long* trow = (const unsigned long long*)&tok_s[kk][0];
            ulonglong2 t0 = *(const ulonglong2*)(trow + tx * 4);
            ulonglong2 t1 = *(const ulonglong2*)(trow + tx * 4 + 2);
            unsigned long long ft[4] = {t0.x, t0.y, t1.x, t1.y};
#pragma unroll
            for (int i = 0; i < 8; i++) {
                float am = attn_s[ty * 8 + i][k0 + kk];
                unsigned long long fm = pack2(am, am);
#pragma unroll
                for (int j = 0; j < 4; j++) acc[i][j] = ffma2(fm, ft[j], acc[i][j]);
            }
        }
    }

#pragma unroll
    for (int i = 0; i < 8; i++) {
        int pp = ty * 8 + i;
        float rm = (float)req_mask[b * P_ + pp];
        float o[8];
#pragma unroll
        for (int j = 0; j < 4; j++) unpack2(acc[i][j], o[2 * j], o[2 * j + 1]);
#pragma unroll
        for (int j = 0; j < 8; j++) o[j] *= rm;
        float* dst = out + ((size_t)bq * P_ + pp) * D_ + tx * 8;
        *(float4*)dst       = make_float4(o[0], o[1], o[2], o[3]);
        *(float4*)(dst + 4) = make_float4(o[4], o[5], o[6], o[7]);
    }
}

// ---------------- launch ----------------
extern "C" void kernel_launch(void* const* d_in, const int* in_sizes, int n_in,
                              void* d_out, int out_size) {
    const float* exp_tokens = (const float*)d_in[0];  // (B,Q,LE,D) f32
    const int*   exp_mask   = (const int*)  d_in[1];  // (B,Q,LE) i32
    const float* s_j        = (const float*)d_in[2];  // (B,P,D) f32
    const int*   req_mask   = (const int*)  d_in[3];  // (B,P) i32
    const float* Ws_w       = (const float*)d_in[4];  // (A,D)
    const float* Ws_b       = (const float*)d_in[5];  // (A,)
    const float* U_w        = (const float*)d_in[6];  // (A,D)
    const float* v_w        = (const float*)d_in[7];  // (1,A)
    float* out = (float*)d_out;                       // (B,Q,P,D) f32

    cudaFuncSetAttribute(k_uh_score, cudaFuncAttributeMaxDynamicSharedMemorySize, SMEM_FUSED);

    k_ws      <<<B_ * P_, 128>>>(s_j, Ws_w, Ws_b);
    k_uh_score<<<B_ * Q_, 256, SMEM_FUSED>>>(exp_tokens, U_w, exp_mask, v_w);
    k_softmax <<<B_ * P_, 256>>>();
    k_out     <<<B_ * Q_, 256>>>(exp_tokens, req_mask, out);
}

// round 5
// speedup vs baseline: 2.4482x; 1.5426x over previous
#include <cuda_runtime.h>
#include <cuda_bf16.h>
#include <cstdint>
#include <cstddef>

#define B_ 8
#define Q_ 32
#define T_ 128   // LE
#define D_ 512
#define P_ 32
#define A_ 128

// Scratch: ws (128KB), e/attn (4MB, layout [b][p][q][t])
__device__ float g_ws[B_ * P_ * A_];
__device__ float g_e[(size_t)B_ * P_ * Q_ * T_];

// ---------------- generic helpers ----------------
__device__ __forceinline__ float fast_tanh(float x) {
    float y; asm("tanh.approx.f32 %0, %1;" : "=f"(y) : "f"(x)); return y;
}
__device__ __forceinline__ unsigned long long pack2(float lo, float hi) {
    unsigned long long r; asm("mov.b64 %0, {%1, %2};" : "=l"(r) : "f"(lo), "f"(hi)); return r;
}
__device__ __forceinline__ void unpack2(unsigned long long v, float& lo, float& hi) {
    asm("mov.b64 {%0, %1}, %2;" : "=f"(lo), "=f"(hi) : "l"(v));
}
__device__ __forceinline__ unsigned long long ffma2(unsigned long long a,
                                                    unsigned long long b,
                                                    unsigned long long c) {
    unsigned long long d;
    asm("fma.rn.f32x2 %0, %1, %2, %3;" : "=l"(d) : "l"(a), "l"(b), "l"(c));
    return d;
}
__device__ __forceinline__ uint32_t smem_u32(const void* p) {
    uint32_t a;
    asm("{ .reg .u64 t; cvta.to.shared.u64 t, %1; cvt.u32.u64 %0, t; }" : "=r"(a) : "l"(p));
    return a;
}
// split f32 pair -> bf16x2 hi + bf16x2 lo   (lo half of reg = first value)
__device__ __forceinline__ void cvt_split(float x0, float x1, uint32_t& h2, uint32_t& l2) {
    asm("cvt.rn.bf16x2.f32 %0, %1, %2;" : "=r"(h2) : "f"(x1), "f"(x0));
    float f0 = __uint_as_float(h2 << 16);
    float f1 = __uint_as_float(h2 & 0xffff0000u);
    float l0 = x0 - f0, l1 = x1 - f1;
    asm("cvt.rn.bf16x2.f32 %0, %1, %2;" : "=r"(l2) : "f"(l1), "f"(l0));
}
__device__ __forceinline__ void ldmx4(uint32_t* r, uint32_t addr) {
    asm volatile("ldmatrix.sync.aligned.m8n8.x4.shared.b16 {%0,%1,%2,%3}, [%4];"
                 : "=r"(r[0]), "=r"(r[1]), "=r"(r[2]), "=r"(r[3]) : "r"(addr));
}
__device__ __forceinline__ void mma_bf16(float* d, const uint32_t* a, const uint32_t* b) {
    asm volatile("mma.sync.aligned.m16n8k16.row.col.f32.bf16.bf16.f32 "
                 "{%0,%1,%2,%3}, {%4,%5,%6,%7}, {%8,%9}, {%0,%1,%2,%3};"
                 : "+f"(d[0]), "+f"(d[1]), "+f"(d[2]), "+f"(d[3])
                 : "r"(a[0]), "r"(a[1]), "r"(a[2]), "r"(a[3]), "r"(b[0]), "r"(b[1]));
}

// ---------------- kernel 1: ws[b,p,a] = s_j[b,p,:] . Ws_w[a,:] + Ws_b[a] ----------------
__global__ void k_ws(const float* __restrict__ s_j,
                     const float* __restrict__ Ws_w,
                     const float* __restrict__ Ws_b) {
    __shared__ float srow[D_];
    int bp = blockIdx.x;
    int a  = threadIdx.x;
    ((float4*)srow)[a] = ((const float4*)(s_j + (size_t)bp * D_))[a];
    __syncthreads();
    const float* w = Ws_w + (size_t)a * D_;
    float acc = 0.f;
#pragma unroll 8
    for (int d = 0; d < D_; d++) acc = fmaf(srow[d], w[d], acc);
    g_ws[bp * A_ + a] = acc + Ws_b[a];
}

// ---------------- fused: HMMA uh GEMM (bf16 hi/lo split) + scores, per (b,q) ----------------
// dyn smem layout (bytes):
//   phase1: A_h [128 rows][40 bf16] @0 (10240) | A_l @10240 | B_h @20480 | B_l @30720
//   phase2: uh_s float[128][130]   @0 (66560)   (overlays phase-1 tiles)
//   66560 : ws_t float[128][32] ([a][p]) 16KB
//   82944 : v_s   float[128]
//   83456 : mask_s int[128]
#define SMEM_FUSED 83968
#define OFF_AH 0
#define OFF_AL 10240
#define OFF_BH 20480
#define OFF_BL 30720
#define UH_STRIDE 130
#define OFF_WS 66560
#define OFF_V  82944
#define OFF_MK 83456

__global__ __launch_bounds__(256, 2) void k_uh_score(const float* __restrict__ tok,
                                                     const float* __restrict__ Uw,
                                                     const int* __restrict__ exp_mask,
                                                     const float* __restrict__ v_w) {
    extern __shared__ char smem[];
    uint32_t sb = smem_u32(smem);
    float* uh_s = (float*)smem;
    float* ws_t = (float*)(smem + OFF_WS);
    float* v_s  = (float*)(smem + OFF_V);
    int*   mask_s = (int*)(smem + OFF_MK);

    int tid = threadIdx.x;
    int wid = tid >> 5, lane = tid & 31;
    int bq = blockIdx.x;
    int b = bq >> 5, q = bq & 31;
    int m0 = bq * 128;

    // preload ws (transposed), v, mask
#pragma unroll
    for (int s = 0; s < 16; s++) {
        int it = s * 256 + tid;          // 0..4095 = p*128 + a
        int pp = it >> 7, aa = it & 127;
        ws_t[aa * 32 + pp] = g_ws[b * (P_ * A_) + it];
    }
    if (tid < 128) {
        v_s[tid] = v_w[tid];
        mask_s[tid] = exp_mask[(b * Q_ + q) * T_ + tid];
    }

    // ---- phase 1: GEMM uh[t][a] = sum_k tok[t,k] * Uw[a,k], bf16 hi/lo HMMA ----
    int wm = wid & 3;        // m group: 32 rows
    int wn = wid >> 2;       // n group: 64 cols
    // ldmatrix per-lane byte offsets (within each tile buffer)
    uint32_t a_lane = (uint32_t)((wm * 32 + (lane & 15)) * 80 + (lane >> 4) * 16);
    uint32_t b_row  = (uint32_t)(wn * 64 + (lane & 7) + ((lane >> 4) & 1) * 8);
    uint32_t b_lane = b_row * 80 + ((lane >> 3) & 1) * 16;

    // conversion mapping: r = tid>>1 (row 0..127), h = tid&1 (k half of 16)
    int cr = tid >> 1, ch = tid & 1;
    uint32_t cdst = (uint32_t)(cr * 80 + ch * 32);

    float acc[16][4];
#pragma unroll
    for (int i = 0; i < 16; i++)
#pragma unroll
        for (int j = 0; j < 4; j++) acc[i][j] = 0.f;

    const float* srcA0 = tok + (size_t)(m0 + cr) * D_ + ch * 16;
    const float* srcB0 = Uw  + (size_t)cr * D_ + ch * 16;

#pragma unroll 1
    for (int c = 0; c < 16; c++) {
        __syncthreads();   // previous iteration's ldmatrix reads done
        const float* sA = srcA0 + c * 32;
        const float* sB = srcB0 + c * 32;
#pragma unroll
        for (int j4 = 0; j4 < 4; j4++) {
            float4 v = *(const float4*)(sA + j4 * 4);
            uint32_t h2, l2;
            uint32_t bo = cdst + j4 * 8;
            cvt_split(v.x, v.y, h2, l2);
            *(uint32_t*)(smem + OFF_AH + bo) = h2;
            *(uint32_t*)(smem + OFF_AL + bo) = l2;
            cvt_split(v.z, v.w, h2, l2);
            *(uint32_t*)(smem + OFF_AH + bo + 4) = h2;
            *(uint32_t*)(smem + OFF_AL + bo + 4) = l2;
        }
#pragma unroll
        for (int j4 = 0; j4 < 4; j4++) {
            float4 v = *(const float4*)(sB + j4 * 4);
            uint32_t h2, l2;
            uint32_t bo = cdst + j4 * 8;
            cvt_split(v.x, v.y, h2, l2);
            *(uint32_t*)(smem + OFF_BH + bo) = h2;
            *(uint32_t*)(smem + OFF_BL + bo) = l2;
            cvt_split(v.z, v.w, h2, l2);
            *(uint32_t*)(smem + OFF_BH + bo + 4) = h2;
            *(uint32_t*)(smem + OFF_BL + bo + 4) = l2;
        }
        __syncthreads();

#pragma unroll
        for (int ks = 0; ks < 2; ks++) {
            uint32_t koff = (uint32_t)(ks * 32);
            uint32_t ah[2][4], al[2][4];
#pragma unroll
            for (int mt = 0; mt < 2; mt++) {
                ldmx4(ah[mt], sb + OFF_AH + a_lane + mt * 1280 + koff);
                ldmx4(al[mt], sb + OFF_AL + a_lane + mt * 1280 + koff);
            }
#pragma unroll
            for (int ng = 0; ng < 4; ng++) {
                uint32_t bh[4], bl[4];
                ldmx4(bh, sb + OFF_BH + b_lane + ng * 1280 + koff);
                ldmx4(bl, sb + OFF_BL + b_lane + ng * 1280 + koff);
#pragma unroll
                for (int mt = 0; mt < 2; mt++)
#pragma unroll
                    for (int nt = 0; nt < 2; nt++) {
                        float* d = acc[mt * 8 + ng * 2 + nt];
                        mma_bf16(d, ah[mt], bh + nt * 2);   // hi*hi
                        mma_bf16(d, al[mt], bh + nt * 2);   // lo*hi
                        mma_bf16(d, ah[mt], bl + nt * 2);   // hi*lo
                    }
            }
        }
    }

    // ---- spill uh fragments to smem (overlays tile buffers) ----
    __syncthreads();
    {
        int r0 = wm * 32 + (lane >> 2);
        int c0 = wn * 64 + (lane & 3) * 2;
#pragma unroll
        for (int mt = 0; mt < 2; mt++)
#pragma unroll
            for (int j = 0; j < 8; j++) {
                float* d = acc[mt * 8 + j];
                int row = r0 + mt * 16;
                int col = c0 + j * 8;
                *(float2*)(uh_s + row * UH_STRIDE + col)       = make_float2(d[0], d[1]);
                *(float2*)(uh_s + (row + 8) * UH_STRIDE + col) = make_float2(d[2], d[3]);
            }
    }
    __syncthreads();

    // ---- phase 2: scores for all 32 p, 128 t ----
    int sub = wid & 3, phalf = wid >> 2;
    int t = sub * 32 + lane;
    const float* urow = uh_s + t * UH_STRIDE;
    const float* wbase = ws_t + phalf * 16;
    float accp[16];
#pragma unroll
    for (int p = 0; p < 16; p++) accp[p] = 0.f;

#pragma unroll 4
    for (int a = 0; a < 128; a++) {
        float u  = urow[a];
        float va = v_s[a];
        const float* wr = wbase + a * 32;
#pragma unroll
        for (int p = 0; p < 16; p++)
            accp[p] = fmaf(va, fast_tanh(u + wr[p]), accp[p]);
    }

    bool dead = (mask_s[t] == 0);
    float* eb = g_e + ((size_t)(b * P_ + phalf * 16) * Q_ + q) * T_ + t;
#pragma unroll
    for (int p = 0; p < 16; p++)
        eb[(size_t)p * (Q_ * T_)] = dead ? -1e9f : accp[p];
}

// ---------------- softmax over 4096 contiguous elems per (b,p), in place ----------------
__global__ __launch_bounds__(256) void k_softmax() {
    __shared__ float red[8];
    int bp = blockIdx.x;
    int tid = threadIdx.x;
    int lane = tid & 31, w = tid >> 5;
    float* e = g_e + (size_t)bp * (Q_ * T_);

    float buf[16];
    float4* ep = (float4*)(e + tid * 16);
#pragma unroll
    for (int j = 0; j < 4; j++) {
        float4 v = ep[j];
        buf[4 * j + 0] = v.x; buf[4 * j + 1] = v.y;
        buf[4 * j + 2] = v.z; buf[4 * j + 3] = v.w;
    }
    float mx = -3.4e38f;
#pragma unroll
    for (int j = 0; j < 16; j++) mx = fmaxf(mx, buf[j]);
#pragma unroll
    for (int o = 16; o > 0; o >>= 1) mx = fmaxf(mx, __shfl_xor_sync(0xffffffffu, mx, o));
    if (lane == 0) red[w] = mx;
    __syncthreads();
    mx = red[0];
#pragma unroll
    for (int i = 1; i < 8; i++) mx = fmaxf(mx, red[i]);

    float sm = 0.f;
#pragma unroll
    for (int j = 0; j < 16; j++) {
        float ex = __expf(buf[j] - mx);
        buf[j] = ex;
        sm += ex;
    }
#pragma unroll
    for (int o = 16; o > 0; o >>= 1) sm += __shfl_xor_sync(0xffffffffu, sm, o);
    __syncthreads();
    if (lane == 0) red[w] = sm;
    __syncthreads();
    sm = 0.f;
#pragma unroll
    for (int i = 0; i < 8; i++) sm += red[i];
    float inv = 1.0f / sm;

#pragma unroll
    for (int j = 0; j < 4; j++)
        ep[j] = make_float4(buf[4 * j + 0] * inv, buf[4 * j + 1] * inv,
                            buf[4 * j + 2] * inv, buf[4 * j + 3] * inv);
}

// ---------------- k_out: out[b,q,p,d] = rmask[b,p] * sum_t attn[b,p,q,t] * tok[b,q,t,d] ---
__global__ __launch_bounds__(256, 2) void k_out(const float* __restrict__ tok,
                                                const int* __restrict__ req_mask,
                                                float* __restrict__ out) {
    __shared__ float attn_s[P_][T_];  // 16KB
    __shared__ float tok_s[16][D_];   // 32KB
    int bq = blockIdx.x;
    int b = bq >> 5, q = bq & 31;
    int tid = threadIdx.x;
    int tx = tid & 63, ty = tid >> 6;

    {
#pragma unroll
        for (int s = 0; s < 4; s++) {
            int id = s * 256 + tid;       // 1024 float4
            int pp = id >> 5, c = id & 31;
            const float* src = g_e + ((size_t)(b * P_ + pp) * Q_ + q) * T_ + c * 4;
            *(float4*)&attn_s[pp][c * 4] = *(const float4*)src;
        }
    }

    unsigned long long acc[8][4];
#pragma unroll
    for (int i = 0; i < 8; i++)
#pragma unroll
        for (int j = 0; j < 4; j++) acc[i][j] = 0ull;

    const float* tb = tok + (size_t)bq * T_ * D_;
    for (int k0 = 0; k0 < T_; k0 += 16) {
        __syncthreads();
#pragma unroll
        for (int s = 0; s < 8; s++) {
            int id = s * 256 + tid;
            int r = id >> 7, c4 = id & 127;
            *(float4*)&tok_s[r][c4 * 4] =
                *(const float4*)(tb + (size_t)(k0 + r) * D_ + c4 * 4);
        }
        __syncthreads();
#pragma unroll
        for (int kk = 0; kk < 16; kk++) {
            const unsigned long long* trow = (const unsigned long long*)&tok_s[kk][0];
            ulonglong2 t0 = *(const ulonglong2*)(trow + tx * 4);
            ulonglong2 t1 = *(const ulonglong2*)(trow + tx * 4 + 2);
            unsigned long long ft[4] = {t0.x, t0.y, t1.x, t1.y};
#pragma unroll
            for (int i = 0; i < 8; i++) {
                float am = attn_s[ty * 8 + i][k0 + kk];
                unsigned long long fm = pack2(am, am);
#pragma unroll
                for (int j = 0; j < 4; j++) acc[i][j] = ffma2(fm, ft[j], acc[i][j]);
            }
        }
    }

#pragma unroll
    for (int i = 0; i < 8; i++) {
        int pp = ty * 8 + i;
        float rm = (float)req_mask[b * P_ + pp];
        float o[8];
#pragma unroll
        for (int j = 0; j < 4; j++) unpack2(acc[i][j], o[2 * j], o[2 * j + 1]);
#pragma unroll
        for (int j = 0; j < 8; j++) o[j] *= rm;
        float* dst = out + ((size_t)bq * P_ + pp) * D_ + tx * 8;
        *(float4*)dst       = make_float4(o[0], o[1], o[2], o[3]);
        *(float4*)(dst + 4) = make_float4(o[4], o[5], o[6], o[7]);
    }
}

// ---------------- launch ----------------
extern "C" void kernel_launch(void* const* d_in, const int* in_sizes, int n_in,
                              void* d_out, int out_size) {
    const float* exp_tokens = (const float*)d_in[0];  // (B,Q,LE,D) f32
    const int*   exp_mask   = (const int*)  d_in[1];  // (B,Q,LE) i32
    const float* s_j        = (const float*)d_in[2];  // (B,P,D) f32
    const int*   req_mask   = (const int*)  d_in[3];  // (B,P) i32
    const float* Ws_w       = (const float*)d_in[4];  // (A,D)
    const float* Ws_b       = (const float*)d_in[5];  // (A,)
    const float* U_w        = (const float*)d_in[6];  // (A,D)
    const float* v_w        = (const float*)d_in[7];  // (1,A)
    float* out = (float*)d_out;                       // (B,Q,P,D) f32

    cudaFuncSetAttribute(k_uh_score, cudaFuncAttributeMaxDynamicSharedMemorySize, SMEM_FUSED);

    k_ws      <<<B_ * P_, 128>>>(s_j, Ws_w, Ws_b);
    k_uh_score<<<B_ * Q_, 256, SMEM_FUSED>>>(exp_tokens, U_w, exp_mask, v_w);
    k_softmax <<<B_ * P_, 256>>>();
    k_out     <<<B_ * Q_, 256>>>(exp_tokens, req_mask, out);
}

// round 8
// speedup vs baseline: 2.6480x; 1.0816x over previous
#include <cuda_runtime.h>
#include <cuda_bf16.h>
#include <cstdint>
#include <cstddef>

#define B_ 8
#define Q_ 32
#define T_ 128   // LE
#define D_ 512
#define P_ 32
#define A_ 128

// Scratch: ws (128KB), e/attn (4MB, layout [b][p][q][t]), Uw bf16 hi/lo (160KB each)
__device__ float g_ws[B_ * P_ * A_];
__device__ float g_e[(size_t)B_ * P_ * Q_ * T_];
// Uw split to bf16, pre-padded 80B rows: [chunk 16][a 128][40 u16 (32 data + 8 pad)]
__device__ __align__(16) uint16_t g_uwh[16 * 128 * 40];
__device__ __align__(16) uint16_t g_uwl[16 * 128 * 40];

// ---------------- generic helpers ----------------
__device__ __forceinline__ float fast_tanh(float x) {
    float y; asm("tanh.approx.f32 %0, %1;" : "=f"(y) : "f"(x)); return y;
}
__device__ __forceinline__ uint32_t smem_u32(const void* p) {
    uint32_t a;
    asm("{ .reg .u64 t; cvta.to.shared.u64 t, %1; cvt.u32.u64 %0, t; }" : "=r"(a) : "l"(p));
    return a;
}
// split f32 pair -> bf16x2 hi + bf16x2 lo   (lo half of reg = first value)
__device__ __forceinline__ void cvt_split(float x0, float x1, uint32_t& h2, uint32_t& l2) {
    asm("cvt.rn.bf16x2.f32 %0, %1, %2;" : "=r"(h2) : "f"(x1), "f"(x0));
    float f0 = __uint_as_float(h2 << 16);
    float f1 = __uint_as_float(h2 & 0xffff0000u);
    float l0 = x0 - f0, l1 = x1 - f1;
    asm("cvt.rn.bf16x2.f32 %0, %1, %2;" : "=r"(l2) : "f"(l1), "f"(l0));
}
__device__ __forceinline__ void ldmx4(uint32_t* r, uint32_t addr) {
    asm volatile("ldmatrix.sync.aligned.m8n8.x4.shared.b16 {%0,%1,%2,%3}, [%4];"
                 : "=r"(r[0]), "=r"(r[1]), "=r"(r[2]), "=r"(r[3]) : "r"(addr));
}
__device__ __forceinline__ void ldmx4t(uint32_t* r, uint32_t addr) {
    asm volatile("ldmatrix.sync.aligned.m8n8.x4.trans.shared.b16 {%0,%1,%2,%3}, [%4];"
                 : "=r"(r[0]), "=r"(r[1]), "=r"(r[2]), "=r"(r[3]) : "r"(addr));
}
__device__ __forceinline__ void mma_bf16(float* d, const uint32_t* a, const uint32_t* b) {
    asm volatile("mma.sync.aligned.m16n8k16.row.col.f32.bf16.bf16.f32 "
                 "{%0,%1,%2,%3}, {%4,%5,%6,%7}, {%8,%9}, {%0,%1,%2,%3};"
                 : "+f"(d[0]), "+f"(d[1]), "+f"(d[2]), "+f"(d[3])
                 : "r"(a[0]), "r"(a[1]), "r"(a[2]), "r"(a[3]), "r"(b[0]), "r"(b[1]));
}

// ---------------- kernel 0: split Uw to bf16 hi/lo, padded layout ----------------
__global__ void k_prep(const float* __restrict__ Uw) {
    int a = blockIdx.x;          // 0..127
    int t = threadIdx.x;         // 0..127
    int k0 = t * 4;
    float4 v = *(const float4*)(Uw + (size_t)a * D_ + k0);
    int c = k0 >> 5, w = k0 & 31;
    uint32_t h0, l0, h1, l1;
    cvt_split(v.x, v.y, h0, l0);
    cvt_split(v.z, v.w, h1, l1);
    char* dh = (char*)g_uwh + (size_t)(c * 128 + a) * 80 + w * 2;
    char* dl = (char*)g_uwl + (size_t)(c * 128 + a) * 80 + w * 2;
    *(uint32_t*)dh = h0; *(uint32_t*)(dh + 4) = h1;
    *(uint32_t*)dl = l0; *(uint32_t*)(dl + 4) = l1;
}

// ---------------- kernel 1: ws[b,p,a] = s_j[b,p,:] . Ws_w[a,:] + Ws_b[a] ----------------
__global__ void k_ws(const float* __restrict__ s_j,
                     const float* __restrict__ Ws_w,
                     const float* __restrict__ Ws_b) {
    __shared__ float srow[D_];
    int bp = blockIdx.x;
    int a  = threadIdx.x;
    ((float4*)srow)[a] = ((const float4*)(s_j + (size_t)bp * D_))[a];
    __syncthreads();
    const float* w = Ws_w + (size_t)a * D_;
    float acc = 0.f;
#pragma unroll 8
    for (int d = 0; d < D_; d++) acc = fmaf(srow[d], w[d], acc);
    g_ws[bp * A_ + a] = acc + Ws_b[a];
}

// ---------------- fused: HMMA uh GEMM (bf16 hi/lo) + scores, per (b,q) ----------------
// dyn smem layout (bytes):
//   phase1: A_h [128][40 bf16] @0 (10240) | A_l @10240 | B_h @20480 | B_l @30720
//   phase2: uh_s float[128][130]  @0 (66560)   (overlays phase-1 tiles)
//   66560 : ws_t float[128][32] ([a][p]) 16KB
//   82944 : v_s   float[128]
//   83456 : mask_s int[128]
#define SMEM_FUSED 83968
#define OFF_AH 0
#define OFF_AL 10240
#define OFF_BH 20480
#define OFF_BL 30720
#define UH_STRIDE 130
#define OFF_WS 66560
#define OFF_V  82944
#define OFF_MK 83456

__global__ __launch_bounds__(256, 2) void k_uh_score(const float* __restrict__ tok,
                                                     const int* __restrict__ exp_mask,
                                                     const float* __restrict__ v_w) {
    extern __shared__ char smem[];
    uint32_t sb = smem_u32(smem);
    float* uh_s = (float*)smem;
    float* ws_t = (float*)(smem + OFF_WS);
    float* v_s  = (float*)(smem + OFF_V);
    int*   mask_s = (int*)(smem + OFF_MK);
    uint32_t* sBH = (uint32_t*)(smem + OFF_BH);
    uint32_t* sBL = (uint32_t*)(smem + OFF_BL);

    int tid = threadIdx.x;
    int wid = tid >> 5, lane = tid & 31;
    int bq = blockIdx.x;
    int b = bq >> 5, q = bq & 31;
    int m0 = bq * 128;

    // preload ws (transposed), v, mask
#pragma unroll
    for (int s = 0; s < 16; s++) {
        int it = s * 256 + tid;          // p*128 + a
        int pp = it >> 7, aa = it & 127;
        ws_t[aa * 32 + pp] = g_ws[b * (P_ * A_) + it];
    }
    if (tid < 128) {
        v_s[tid] = v_w[tid];
        mask_s[tid] = exp_mask[(b * Q_ + q) * T_ + tid];
    }

    // ---- phase 1: GEMM uh[t][a] = sum_k tok[t,k] * Uw[a,k] ----
    int wm = wid & 3;        // m group: 32 rows
    int wn = wid >> 2;       // n group: 64 cols
    uint32_t a_lane = (uint32_t)((wm * 32 + (lane & 15)) * 80 + (lane >> 4) * 16);
    uint32_t b_row  = (uint32_t)(wn * 64 + (lane & 7) + ((lane >> 4) & 1) * 8);
    uint32_t b_lane = b_row * 80 + ((lane >> 3) & 1) * 16;

    // conversion mapping: r = tid>>1 (row 0..127), h = tid&1 (k half of 32)
    int cr = tid >> 1, ch = tid & 1;
    uint32_t cdst = (uint32_t)(cr * 80 + ch * 32);

    float acc[16][4];
#pragma unroll
    for (int i = 0; i < 16; i++)
#pragma unroll
        for (int j = 0; j < 4; j++) acc[i][j] = 0.f;

    const float* srcA0 = tok + (size_t)(m0 + cr) * D_ + ch * 16;
    const uint32_t* uwh32 = (const uint32_t*)g_uwh;
    const uint32_t* uwl32 = (const uint32_t*)g_uwl;

    // prime chunk-0 A prefetch
    float4 pa[4];
#pragma unroll
    for (int j = 0; j < 4; j++) pa[j] = *(const float4*)(srcA0 + j * 4);

#pragma unroll 1
    for (int c = 0; c < 16; c++) {
        // convert prefetched A regs -> smem tiles
#pragma unroll
        for (int j4 = 0; j4 < 4; j4++) {
            uint32_t h2, l2;
            uint32_t bo = cdst + j4 * 8;
            cvt_split(pa[j4].x, pa[j4].y, h2, l2);
            *(uint32_t*)(smem + OFF_AH + bo) = h2;
            *(uint32_t*)(smem + OFF_AL + bo) = l2;
            cvt_split(pa[j4].z, pa[j4].w, h2, l2);
            *(uint32_t*)(smem + OFF_AH + bo + 4) = h2;
            *(uint32_t*)(smem + OFF_AL + bo + 4) = l2;
        }
        // copy B tiles (pre-split, pre-padded; L2-hot)
        {
            const uint32_t* srcH = uwh32 + c * 2560 + tid;
            const uint32_t* srcL = uwl32 + c * 2560 + tid;
#pragma unroll
            for (int j = 0; j < 10; j++) {
                sBH[j * 256 + tid] = srcH[j * 256];
                sBL[j * 256 + tid] = srcL[j * 256];
            }
        }
        // prefetch next A chunk (overlaps with MMA below)
        if (c < 15) {
            const float* nsrc = srcA0 + (c + 1) * 32;
#pragma unroll
            for (int j = 0; j < 4; j++) pa[j] = *(const float4*)(nsrc + j * 4);
        }
        __syncthreads();

#pragma unroll
        for (int ks = 0; ks < 2; ks++) {
            uint32_t koff = (uint32_t)(ks * 32);
            uint32_t ah[2][4], al[2][4];
#pragma unroll
            for (int mt = 0; mt < 2; mt++) {
                ldmx4(ah[mt], sb + OFF_AH + a_lane + mt * 1280 + koff);
                ldmx4(al[mt], sb + OFF_AL + a_lane + mt * 1280 + koff);
            }
#pragma unroll
            for (int ng = 0; ng < 4; ng++) {
                uint32_t bh[4], bl[4];
                ldmx4(bh, sb + OFF_BH + b_lane + ng * 1280 + koff);
                ldmx4(bl, sb + OFF_BL + b_lane + ng * 1280 + koff);
#pragma unroll
                for (int mt = 0; mt < 2; mt++)
#pragma unroll
                    for (int nt = 0; nt < 2; nt++) {
                        float* d = acc[mt * 8 + ng * 2 + nt];
                        mma_bf16(d, ah[mt], bh + nt * 2);   // hi*hi
                        mma_bf16(d, al[mt], bh + nt * 2);   // lo*hi
                        mma_bf16(d, ah[mt], bl + nt * 2);   // hi*lo
                    }
            }
        }
        __syncthreads();
    }

    // ---- spill uh fragments to smem (overlays tile buffers) ----
    {
        int r0 = wm * 32 + (lane >> 2);
        int c0 = wn * 64 + (lane & 3) * 2;
#pragma unroll
        for (int mt = 0; mt < 2; mt++)
#pragma unroll
            for (int j = 0; j < 8; j++) {
                float* d = acc[mt * 8 + j];
                int row = r0 + mt * 16;
                int col = c0 + j * 8;
                *(float2*)(uh_s + row * UH_STRIDE + col)       = make_float2(d[0], d[1]);
                *(float2*)(uh_s + (row + 8) * UH_STRIDE + col) = make_float2(d[2], d[3]);
            }
    }
    __syncthreads();

    // ---- phase 2: scores for all 32 p, 128 t ----
    int sub = wid & 3, phalf = wid >> 2;
    int t = sub * 32 + lane;
    const float* urow = uh_s + t * UH_STRIDE;
    const float* wbase = ws_t + phalf * 16;
    float accp[16];
#pragma unroll
    for (int p = 0; p < 16; p++) accp[p] = 0.f;

#pragma unroll 4
    for (int a = 0; a < 128; a++) {
        float u  = urow[a];
        float va = v_s[a];
        const float* wr = wbase + a * 32;
#pragma unroll
        for (int p = 0; p < 16; p++)
            accp[p] = fmaf(va, fast_tanh(u + wr[p]), accp[p]);
    }

    bool dead = (mask_s[t] == 0);
    float* eb = g_e + ((size_t)(b * P_ + phalf * 16) * Q_ + q) * T_ + t;
#pragma unroll
    for (int p = 0; p < 16; p++)
        eb[(size_t)p * (Q_ * T_)] = dead ? -1e9f : accp[p];
}

// ---------------- softmax over 4096 contiguous elems per (b,p), in place ----------------
__global__ __launch_bounds__(256) void k_softmax() {
    __shared__ float red[8];
    int bp = blockIdx.x;
    int tid = threadIdx.x;
    int lane = tid & 31, w = tid >> 5;
    float* e = g_e + (size_t)bp * (Q_ * T_);

    float buf[16];
    float4* ep = (float4*)(e + tid * 16);
#pragma unroll
    for (int j = 0; j < 4; j++) {
        float4 v = ep[j];
        buf[4 * j + 0] = v.x; buf[4 * j + 1] = v.y;
        buf[4 * j + 2] = v.z; buf[4 * j + 3] = v.w;
    }
    float mx = -3.4e38f;
#pragma unroll
    for (int j = 0; j < 16; j++) mx = fmaxf(mx, buf[j]);
#pragma unroll
    for (int o = 16; o > 0; o >>= 1) mx = fmaxf(mx, __shfl_xor_sync(0xffffffffu, mx, o));
    if (lane == 0) red[w] = mx;
    __syncthreads();
    mx = red[0];
#pragma unroll
    for (int i = 1; i < 8; i++) mx = fmaxf(mx, red[i]);

    float sm = 0.f;
#pragma unroll
    for (int j = 0; j < 16; j++) {
        float ex = __expf(buf[j] - mx);
        buf[j] = ex;
        sm += ex;
    }
#pragma unroll
    for (int o = 16; o > 0; o >>= 1) sm += __shfl_xor_sync(0xffffffffu, sm, o);
    __syncthreads();
    if (lane == 0) red[w] = sm;
    __syncthreads();
    sm = 0.f;
#pragma unroll
    for (int i = 0; i < 8; i++) sm += red[i];
    float inv = 1.0f / sm;

#pragma unroll
    for (int j = 0; j < 4; j++)
        ep[j] = make_float4(buf[4 * j + 0] * inv, buf[4 * j + 1] * inv,
                            buf[4 * j + 2] * inv, buf[4 * j + 3] * inv);
}

// ---------------- k_out (HMMA): out[b,q,p,d] = rmask * attn(32x128) x tok(128x512) ----
// dyn smem: attn_h @0 (32*272=8704) | attn_l @8704 | tok_h @17408 (16*1040=16640) | tok_l @34048
#define KO_AH 0
#define KO_AL 8704
#define KO_TH 17408
#define KO_TL 34048
#define KO_SMEM 50688

__global__ __launch_bounds__(256, 2) void k_out(const float* __restrict__ tok,
                                                const int* __restrict__ req_mask,
                                                float* __restrict__ out) {
    extern __shared__ char smem[];
    uint32_t sb = smem_u32(smem);
    int bq = blockIdx.x;
    int b = bq >> 5, q = bq & 31;
    int tid = threadIdx.x;
    int wid = tid >> 5, lane = tid & 31;

    // ---- load + convert attn (32 p x 128 t) once: 1024 float4 total ----
#pragma unroll
    for (int s = 0; s < 4; s++) {
        int idx = s * 256 + tid;          // 0..1023
        int r  = idx >> 5;                // p row 0..31
        int c4 = idx & 31;                // float4 index within row
        const float* src = g_e + ((size_t)(b * P_ + r) * Q_ + q) * T_ + c4 * 4;
        float4 v = *(const float4*)src;
        uint32_t h0, l0, h1, l1;
        cvt_split(v.x, v.y, h0, l0);
        cvt_split(v.z, v.w, h1, l1);
        uint32_t bo = (uint32_t)(r * 272 + c4 * 8);
        *(uint32_t*)(smem + KO_AH + bo)     = h0;
        *(uint32_t*)(smem + KO_AH + bo + 4) = h1;
        *(uint32_t*)(smem + KO_AL + bo)     = l0;
        *(uint32_t*)(smem + KO_AL + bo + 4) = l1;
    }

    int wm = wid & 1;        // m tile: 16 p rows
    int wn = wid >> 1;       // n group: 128 d cols
    uint32_t a_lane = (uint32_t)((wm * 16 + (lane & 15)) * 272 + (lane >> 4) * 16);
    // trans-ldmatrix lane mapping for tok B tiles
    int bmat = lane >> 3;
    uint32_t bt_row = (uint32_t)((bmat & 1) * 8 + (lane & 7));
    uint32_t bt_col = (uint32_t)((bmat >> 1) * 8);

    // conversion mapping: r = tid&15 (t row), seg = tid>>4 (32 d cols)
    int cvr = tid & 15, cvs = tid >> 4;

    float acc[16][4];
#pragma unroll
    for (int i = 0; i < 16; i++)
#pragma unroll
        for (int j = 0; j < 4; j++) acc[i][j] = 0.f;

    const float* tb = tok + (size_t)bq * T_ * D_;

#pragma unroll 1
    for (int c = 0; c < 8; c++) {
        // convert tok chunk (16 t x 512 d)
        const float* src = tb + (size_t)(c * 16 + cvr) * D_ + cvs * 32;
        uint32_t bo0 = (uint32_t)(cvr * 1040 + cvs * 64);
#pragma unroll
        for (int j4 = 0; j4 < 8; j4++) {
            float4 v = *(const float4*)(src + j4 * 4);
            uint32_t h2, l2;
            uint32_t bo = bo0 + j4 * 8;
            cvt_split(v.x, v.y, h2, l2);
            *(uint32_t*)(smem + KO_TH + bo) = h2;
            *(uint32_t*)(smem + KO_TL + bo) = l2;
            cvt_split(v.z, v.w, h2, l2);
            *(uint32_t*)(smem + KO_TH + bo + 4) = h2;
            *(uint32_t*)(smem + KO_TL + bo + 4) = l2;
        }
        __syncthreads();

        uint32_t ah[4], al[4];
        ldmx4(ah, sb + KO_AH + a_lane + c * 32);
        ldmx4(al, sb + KO_AL + a_lane + c * 32);
#pragma unroll
        for (int ng = 0; ng < 8; ng++) {
            uint32_t n0 = (uint32_t)(wn * 128 + ng * 16);
            uint32_t baddr = bt_row * 1040 + (n0 + bt_col) * 2;
            uint32_t bh[4], bl[4];
            ldmx4t(bh, sb + KO_TH + baddr);
            ldmx4t(bl, sb + KO_TL + baddr);
#pragma unroll
            for (int nt = 0; nt < 2; nt++) {
                float* d = acc[ng * 2 + nt];
                mma_bf16(d, ah, bh + nt * 2);
                mma_bf16(d, al, bh + nt * 2);
                mma_bf16(d, ah, bl + nt * 2);
            }
        }
        __syncthreads();
    }

    // ---- epilogue ----
    int r0 = wm * 16 + (lane >> 2);
    int c0 = wn * 128 + (lane & 3) * 2;
    float rm0 = (float)req_mask[b * P_ + r0];
    float rm1 = (float)req_mask[b * P_ + r0 + 8];
    float* ob = out + (size_t)bq * P_ * D_;
#pragma unroll
    for (int i = 0; i < 16; i++) {
        float* d = acc[i];
        int col = c0 + (i >> 1) * 16 + (i & 1) * 8;
        *(float2*)(ob + (size_t)r0 * D_ + col)       = make_float2(d[0] * rm0, d[1] * rm0);
        *(float2*)(ob + (size_t)(r0 + 8) * D_ + col) = make_float2(d[2] * rm1, d[3] * rm1);
    }
}

// ---------------- launch ----------------
extern "C" void kernel_launch(void* const* d_in, const int* in_sizes, int n_in,
                              void* d_out, int out_size) {
    const float* exp_tokens = (const float*)d_in[0];  // (B,Q,LE,D) f32
    const int*   exp_mask   = (const int*)  d_in[1];  // (B,Q,LE) i32
    const float* s_j        = (const float*)d_in[2];  // (B,P,D) f32
    const int*   req_mask   = (const int*)  d_in[3];  // (B,P) i32
    const float* Ws_w       = (const float*)d_in[4];  // (A,D)
    const float* Ws_b       = (const float*)d_in[5];  // (A,)
    const float* U_w        = (const float*)d_in[6];  // (A,D)
    const float* v_w        = (const float*)d_in[7];  // (1,A)
    float* out = (float*)d_out;                       // (B,Q,P,D) f32

    cudaFuncSetAttribute(k_uh_score, cudaFuncAttributeMaxDynamicSharedMemorySize, SMEM_FUSED);
    cudaFuncSetAttribute(k_out, cudaFuncAttributeMaxDynamicSharedMemorySize, KO_SMEM);

    k_prep    <<<128, 128>>>(U_w);
    k_ws      <<<B_ * P_, 128>>>(s_j, Ws_w, Ws_b);
    k_uh_score<<<B_ * Q_, 256, SMEM_FUSED>>>(exp_tokens, exp_mask, v_w);
    k_softmax <<<B_ * P_, 256>>>();
    k_out     <<<B_ * Q_, 256, KO_SMEM>>>(exp_tokens, req_mask, out);
}

// round 10
// speedup vs baseline: 2.8125x; 1.0621x over previous
#include <cuda_runtime.h>
#include <cuda_bf16.h>
#include <cuda_fp16.h>
#include <cstdint>
#include <cstddef>

#define B_ 8
#define Q_ 32
#define T_ 128   // LE
#define D_ 512
#define P_ 32
#define A_ 128

// Scratch: ws (128KB), e/attn (4MB, layout [b][p][q][t]), Uw fp16 (160KB)
__device__ float g_ws[B_ * P_ * A_];
__device__ float g_e[(size_t)B_ * P_ * Q_ * T_];
// Uw as fp16, pre-padded 80B rows: [chunk 16][a 128][40 u16 (32 data + 8 pad)]
__device__ __align__(16) uint16_t g_uwh[16 * 128 * 40];

// ---------------- generic helpers ----------------
__device__ __forceinline__ float fast_tanh(float x) {
    float y; asm("tanh.approx.f32 %0, %1;" : "=f"(y) : "f"(x)); return y;
}
__device__ __forceinline__ uint32_t smem_u32(const void* p) {
    uint32_t a;
    asm("{ .reg .u64 t; cvta.to.shared.u64 t, %1; cvt.u32.u64 %0, t; }" : "=r"(a) : "l"(p));
    return a;
}
// f32 pair -> fp16x2 (rn)
__device__ __forceinline__ uint32_t cvt_f16x2(float x0, float x1) {
    __half2 h = __floats2half2_rn(x0, x1);
    return *reinterpret_cast<uint32_t*>(&h);
}
// split f32 pair -> fp16x2 hi + fp16x2 lo (hi+lo reconstructs to ~2^-22)
__device__ __forceinline__ void cvt_split_f16(float x0, float x1, uint32_t& h2, uint32_t& l2) {
    __half2 h = __floats2half2_rn(x0, x1);
    float2 hf = __half22float2(h);
    __half2 l = __floats2half2_rn(x0 - hf.x, x1 - hf.y);
    h2 = *reinterpret_cast<uint32_t*>(&h);
    l2 = *reinterpret_cast<uint32_t*>(&l);
}
__device__ __forceinline__ void ldmx4(uint32_t* r, uint32_t addr) {
    asm volatile("ldmatrix.sync.aligned.m8n8.x4.shared.b16 {%0,%1,%2,%3}, [%4];"
                 : "=r"(r[0]), "=r"(r[1]), "=r"(r[2]), "=r"(r[3]) : "r"(addr));
}
__device__ __forceinline__ void ldmx4t(uint32_t* r, uint32_t addr) {
    asm volatile("ldmatrix.sync.aligned.m8n8.x4.trans.shared.b16 {%0,%1,%2,%3}, [%4];"
                 : "=r"(r[0]), "=r"(r[1]), "=r"(r[2]), "=r"(r[3]) : "r"(addr));
}
__device__ __forceinline__ void mma_f16(float* d, const uint32_t* a, const uint32_t* b) {
    asm volatile("mma.sync.aligned.m16n8k16.row.col.f32.f16.f16.f32 "
                 "{%0,%1,%2,%3}, {%4,%5,%6,%7}, {%8,%9}, {%0,%1,%2,%3};"
                 : "+f"(d[0]), "+f"(d[1]), "+f"(d[2]), "+f"(d[3])
                 : "r"(a[0]), "r"(a[1]), "r"(a[2]), "r"(a[3]), "r"(b[0]), "r"(b[1]));
}

// ---------------- kernel 0: Uw -> fp16, padded layout ----------------
__global__ void k_prep(const float* __restrict__ Uw) {
    int a = blockIdx.x;          // 0..127
    int t = threadIdx.x;         // 0..127
    int k0 = t * 4;
    float4 v = *(const float4*)(Uw + (size_t)a * D_ + k0);
    int c = k0 >> 5, w = k0 & 31;
    uint32_t u0 = cvt_f16x2(v.x, v.y);
    uint32_t u1 = cvt_f16x2(v.z, v.w);
    char* dh = (char*)g_uwh + (size_t)(c * 128 + a) * 80 + w * 2;
    *(uint32_t*)dh = u0; *(uint32_t*)(dh + 4) = u1;
}

// ---------------- kernel 1: ws[b,p,a] = s_j[b,p,:] . Ws_w[a,:] + Ws_b[a] ----------------
__global__ void k_ws(const float* __restrict__ s_j,
                     const float* __restrict__ Ws_w,
                     const float* __restrict__ Ws_b) {
    __shared__ float srow[D_];
    int bp = blockIdx.x;
    int a  = threadIdx.x;
    ((float4*)srow)[a] = ((const float4*)(s_j + (size_t)bp * D_))[a];
    __syncthreads();
    const float* w = Ws_w + (size_t)a * D_;
    float acc = 0.f;
#pragma unroll 8
    for (int d = 0; d < D_; d++) acc = fmaf(srow[d], w[d], acc);
    g_ws[bp * A_ + a] = acc + Ws_b[a];
}

// ---------------- fused: HMMA uh GEMM (fp16 2-term) + scores, per (b,q) ----------------
// dyn smem layout (bytes):
//   phase1: A_h [128][40 f16] @0 (10240) | A_l @10240 | B_h @20480 (10240)
//   phase2: uh_s float[128][130]  @0 (66560)   (overlays phase-1 tiles)
//   66560 : ws_t float[128][32] ([a][p]) 16KB
//   82944 : v_s   float[128]
//   83456 : mask_s int[128]
#define SMEM_FUSED 83968
#define OFF_AH 0
#define OFF_AL 10240
#define OFF_BH 20480
#define UH_STRIDE 130
#define OFF_WS 66560
#define OFF_V  82944
#define OFF_MK 83456

__global__ __launch_bounds__(256, 2) void k_uh_score(const float* __restrict__ tok,
                                                     const int* __restrict__ exp_mask,
                                                     const float* __restrict__ v_w) {
    extern __shared__ char smem[];
    uint32_t sb = smem_u32(smem);
    float* uh_s = (float*)smem;
    float* ws_t = (float*)(smem + OFF_WS);
    float* v_s  = (float*)(smem + OFF_V);
    int*   mask_s = (int*)(smem + OFF_MK);
    uint32_t* sBH = (uint32_t*)(smem + OFF_BH);

    int tid = threadIdx.x;
    int wid = tid >> 5, lane = tid & 31;
    int bq = blockIdx.x;
    int b = bq >> 5, q = bq & 31;
    int m0 = bq * 128;

    // preload ws (transposed), v, mask
#pragma unroll
    for (int s = 0; s < 16; s++) {
        int it = s * 256 + tid;          // p*128 + a
        int pp = it >> 7, aa = it & 127;
        ws_t[aa * 32 + pp] = g_ws[b * (P_ * A_) + it];
    }
    if (tid < 128) {
        v_s[tid] = v_w[tid];
        mask_s[tid] = exp_mask[(b * Q_ + q) * T_ + tid];
    }

    // ---- phase 1: GEMM uh[t][a] = sum_k tok[t,k] * Uw[a,k] ----
    int wm = wid & 3;        // m group: 32 rows
    int wn = wid >> 2;       // n group: 64 cols
    uint32_t a_lane = (uint32_t)((wm * 32 + (lane & 15)) * 80 + (lane >> 4) * 16);
    uint32_t b_row  = (uint32_t)(wn * 64 + (lane & 7) + ((lane >> 4) & 1) * 8);
    uint32_t b_lane = b_row * 80 + ((lane >> 3) & 1) * 16;

    // conversion mapping: r = tid>>1 (row 0..127), h = tid&1 (k half of 32)
    int cr = tid >> 1, ch = tid & 1;
    uint32_t cdst = (uint32_t)(cr * 80 + ch * 32);

    float acc[16][4];
#pragma unroll
    for (int i = 0; i < 16; i++)
#pragma unroll
        for (int j = 0; j < 4; j++) acc[i][j] = 0.f;

    const float* srcA0 = tok + (size_t)(m0 + cr) * D_ + ch * 16;
    const uint32_t* uwh32 = (const uint32_t*)g_uwh;

    // prime chunk-0 A prefetch
    float4 pa[4];
#pragma unroll
    for (int j = 0; j < 4; j++) pa[j] = *(const float4*)(srcA0 + j * 4);

#pragma unroll 1
    for (int c = 0; c < 16; c++) {
        // convert prefetched A regs -> smem hi/lo tiles
#pragma unroll
        for (int j4 = 0; j4 < 4; j4++) {
            uint32_t h2, l2;
            uint32_t bo = cdst + j4 * 8;
            cvt_split_f16(pa[j4].x, pa[j4].y, h2, l2);
            *(uint32_t*)(smem + OFF_AH + bo) = h2;
            *(uint32_t*)(smem + OFF_AL + bo) = l2;
            cvt_split_f16(pa[j4].z, pa[j4].w, h2, l2);
            *(uint32_t*)(smem + OFF_AH + bo + 4) = h2;
            *(uint32_t*)(smem + OFF_AL + bo + 4) = l2;
        }
        // copy B tile (pre-converted fp16, L2-hot)
        {
            const uint32_t* srcH = uwh32 + c * 2560 + tid;
#pragma unroll
            for (int j = 0; j < 10; j++) sBH[j * 256 + tid] = srcH[j * 256];
        }
        // prefetch next A chunk (overlaps with MMA below)
        if (c < 15) {
            const float* nsrc = srcA0 + (c + 1) * 32;
#pragma unroll
            for (int j = 0; j < 4; j++) pa[j] = *(const float4*)(nsrc + j * 4);
        }
        __syncthreads();

#pragma unroll
        for (int ks = 0; ks < 2; ks++) {
            uint32_t koff = (uint32_t)(ks * 32);
            uint32_t ah[2][4], al[2][4];
#pragma unroll
            for (int mt = 0; mt < 2; mt++) {
                ldmx4(ah[mt], sb + OFF_AH + a_lane + mt * 1280 + koff);
                ldmx4(al[mt], sb + OFF_AL + a_lane + mt * 1280 + koff);
            }
#pragma unroll
            for (int ng = 0; ng < 4; ng++) {
                uint32_t bh[4];
                ldmx4(bh, sb + OFF_BH + b_lane + ng * 1280 + koff);
#pragma unroll
                for (int mt = 0; mt < 2; mt++)
#pragma unroll
                    for (int nt = 0; nt < 2; nt++) {
                        float* d = acc[mt * 8 + ng * 2 + nt];
                        mma_f16(d, ah[mt], bh + nt * 2);   // hi * B
                        mma_f16(d, al[mt], bh + nt * 2);   // lo * B
                    }
            }
        }
        __syncthreads();
    }

    // ---- spill uh fragments to smem (overlays tile buffers) ----
    {
        int r0 = wm * 32 + (lane >> 2);
        int c0 = wn * 64 + (lane & 3) * 2;
#pragma unroll
        for (int mt = 0; mt < 2; mt++)
#pragma unroll
            for (int j = 0; j < 8; j++) {
                float* d = acc[mt * 8 + j];
                int row = r0 + mt * 16;
                int col = c0 + j * 8;
                *(float2*)(uh_s + row * UH_STRIDE + col)       = make_float2(d[0], d[1]);
                *(float2*)(uh_s + (row + 8) * UH_STRIDE + col) = make_float2(d[2], d[3]);
            }
    }
    __syncthreads();

    // ---- phase 2: scores for all 32 p, 128 t ----
    int sub = wid & 3, phalf = wid >> 2;
    int t = sub * 32 + lane;
    const float* urow = uh_s + t * UH_STRIDE;
    const float* wbase = ws_t + phalf * 16;
    float accp[16];
#pragma unroll
    for (int p = 0; p < 16; p++) accp[p] = 0.f;

#pragma unroll 4
    for (int a = 0; a < 128; a++) {
        float u  = urow[a];
        float va = v_s[a];
        const float* wr = wbase + a * 32;
#pragma unroll
        for (int p = 0; p < 16; p++)
            accp[p] = fmaf(va, fast_tanh(u + wr[p]), accp[p]);
    }

    bool dead = (mask_s[t] == 0);
    float* eb = g_e + ((size_t)(b * P_ + phalf * 16) * Q_ + q) * T_ + t;
#pragma unroll
    for (int p = 0; p < 16; p++)
        eb[(size_t)p * (Q_ * T_)] = dead ? -1e9f : accp[p];
}

// ---------------- softmax over 4096 contiguous elems per (b,p), in place ----------------
__global__ __launch_bounds__(256) void k_softmax() {
    __shared__ float red[8];
    int bp = blockIdx.x;
    int tid = threadIdx.x;
    int lane = tid & 31, w = tid >> 5;
    float* e = g_e + (size_t)bp * (Q_ * T_);

    float buf[16];
    float4* ep = (float4*)(e + tid * 16);
#pragma unroll
    for (int j = 0; j < 4; j++) {
        float4 v = ep[j];
        buf[4 * j + 0] = v.x; buf[4 * j + 1] = v.y;
        buf[4 * j + 2] = v.z; buf[4 * j + 3] = v.w;
    }
    float mx = -3.4e38f;
#pragma unroll
    for (int j = 0; j < 16; j++) mx = fmaxf(mx, buf[j]);
#pragma unroll
    for (int o = 16; o > 0; o >>= 1) mx = fmaxf(mx, __shfl_xor_sync(0xffffffffu, mx, o));
    if (lane == 0) red[w] = mx;
    __syncthreads();
    mx = red[0];
#pragma unroll
    for (int i = 1; i < 8; i++) mx = fmaxf(mx, red[i]);

    float sm = 0.f;
#pragma unroll
    for (int j = 0; j < 16; j++) {
        float ex = __expf(buf[j] - mx);
        buf[j] = ex;
        sm += ex;
    }
#pragma unroll
    for (int o = 16; o > 0; o >>= 1) sm += __shfl_xor_sync(0xffffffffu, sm, o);
    __syncthreads();
    if (lane == 0) red[w] = sm;
    __syncthreads();
    sm = 0.f;
#pragma unroll
    for (int i = 0; i < 8; i++) sm += red[i];
    float inv = 1.0f / sm;

#pragma unroll
    for (int j = 0; j < 4; j++)
        ep[j] = make_float4(buf[4 * j + 0] * inv, buf[4 * j + 1] * inv,
                            buf[4 * j + 2] * inv, buf[4 * j + 3] * inv);
}

// ---------------- k_out (HMMA fp16 2-term): out = rmask * attn(32x128) x tok(128x512) ----
// dyn smem: attn_h @0 (32*272=8704) | attn_l @8704 | tok_h @17408 (16*1040=16640)
#define KO_AH 0
#define KO_AL 8704
#define KO_TH 17408
#define KO_SMEM 34048

__global__ __launch_bounds__(256, 2) void k_out(const float* __restrict__ tok,
                                                const int* __restrict__ req_mask,
                                                float* __restrict__ out) {
    extern __shared__ char smem[];
    uint32_t sb = smem_u32(smem);
    int bq = blockIdx.x;
    int b = bq >> 5, q = bq & 31;
    int tid = threadIdx.x;
    int wid = tid >> 5, lane = tid & 31;

    // ---- load + convert attn (32 p x 128 t) once: 1024 float4 total ----
#pragma unroll
    for (int s = 0; s < 4; s++) {
        int idx = s * 256 + tid;          // 0..1023
        int r  = idx >> 5;                // p row 0..31
        int c4 = idx & 31;                // float4 index within row
        const float* src = g_e + ((size_t)(b * P_ + r) * Q_ + q) * T_ + c4 * 4;
        float4 v = *(const float4*)src;
        uint32_t h0, l0, h1, l1;
        cvt_split_f16(v.x, v.y, h0, l0);
        cvt_split_f16(v.z, v.w, h1, l1);
        uint32_t bo = (uint32_t)(r * 272 + c4 * 8);
        *(uint32_t*)(smem + KO_AH + bo)     = h0;
        *(uint32_t*)(smem + KO_AH + bo + 4) = h1;
        *(uint32_t*)(smem + KO_AL + bo)     = l0;
        *(uint32_t*)(smem + KO_AL + bo + 4) = l1;
    }

    int wm = wid & 1;        // m tile: 16 p rows
    int wn = wid >> 1;       // n group: 128 d cols
    uint32_t a_lane = (uint32_t)((wm * 16 + (lane & 15)) * 272 + (lane >> 4) * 16);
    // trans-ldmatrix lane mapping for tok B tiles
    int bmat = lane >> 3;
    uint32_t bt_row = (uint32_t)((bmat & 1) * 8 + (lane & 7));
    uint32_t bt_col = (uint32_t)((bmat >> 1) * 8);

    // conversion mapping: r = tid&15 (t row), seg = tid>>4 (32 d cols)
    int cvr = tid & 15, cvs = tid >> 4;

    float acc[16][4];
#pragma unroll
    for (int i = 0; i < 16; i++)
#pragma unroll
        for (int j = 0; j < 4; j++) acc[i][j] = 0.f;

    const float* tb = tok + (size_t)bq * T_ * D_;

#pragma unroll 1
    for (int c = 0; c < 8; c++) {
        // convert tok chunk (16 t x 512 d), fp16 hi only
        const float* src = tb + (size_t)(c * 16 + cvr) * D_ + cvs * 32;
        uint32_t bo0 = (uint32_t)(cvr * 1040 + cvs * 64);
#pragma unroll
        for (int j4 = 0; j4 < 8; j4++) {
            float4 v = *(const float4*)(src + j4 * 4);
            uint32_t bo = bo0 + j4 * 8;
            *(uint32_t*)(smem + KO_TH + bo)     = cvt_f16x2(v.x, v.y);
            *(uint32_t*)(smem + KO_TH + bo + 4) = cvt_f16x2(v.z, v.w);
        }
        __syncthreads();

        uint32_t ah[4], al[4];
        ldmx4(ah, sb + KO_AH + a_lane + c * 32);
        ldmx4(al, sb + KO_AL + a_lane + c * 32);
#pragma unroll
        for (int ng = 0; ng < 8; ng++) {
            uint32_t n0 = (uint32_t)(wn * 128 + ng * 16);
            uint32_t baddr = bt_row * 1040 + (n0 + bt_col) * 2;
            uint32_t bh[4];
            ldmx4t(bh, sb + KO_TH + baddr);
#pragma unroll
            for (int nt = 0; nt < 2; nt++) {
                float* d = acc[ng * 2 + nt];
                mma_f16(d, ah, bh + nt * 2);
                mma_f16(d, al, bh + nt * 2);
            }
        }
        __syncthreads();
    }

    // ---- epilogue ----
    int r0 = wm * 16 + (lane >> 2);
    int c0 = wn * 128 + (lane & 3) * 2;
    float rm0 = (float)req_mask[b * P_ + r0];
    float rm1 = (float)req_mask[b * P_ + r0 + 8];
    float* ob = out + (size_t)bq * P_ * D_;
#pragma unroll
    for (int i = 0; i < 16; i++) {
        float* d = acc[i];
        int col = c0 + (i >> 1) * 16 + (i & 1) * 8;
        *(float2*)(ob + (size_t)r0 * D_ + col)       = make_float2(d[0] * rm0, d[1] * rm0);
        *(float2*)(ob + (size_t)(r0 + 8) * D_ + col) = make_float2(d[2] * rm1, d[3] * rm1);
    }
}

// ---------------- launch ----------------
extern "C" void kernel_launch(void* const* d_in, const int* in_sizes, int n_in,
                              void* d_out, int out_size) {
    const float* exp_tokens = (const float*)d_in[0];  // (B,Q,LE,D) f32
    const int*   exp_mask   = (const int*)  d_in[1];  // (B,Q,LE) i32
    const float* s_j        = (const float*)d_in[2];  // (B,P,D) f32
    const int*   req_mask   = (const int*)  d_in[3];  // (B,P) i32
    const float* Ws_w       = (const float*)d_in[4];  // (A,D)
    const float* Ws_b       = (const float*)d_in[5];  // (A,)
    const float* U_w        = (const float*)d_in[6];  // (A,D)
    const float* v_w        = (const float*)d_in[7];  // (1,A)
    float* out = (float*)d_out;                       // (B,Q,P,D) f32

    cudaFuncSetAttribute(k_uh_score, cudaFuncAttributeMaxDynamicSharedMemorySize, SMEM_FUSED);
    cudaFuncSetAttribute(k_out, cudaFuncAttributeMaxDynamicSharedMemorySize, KO_SMEM);

    k_prep    <<<128, 128>>>(U_w);
    k_ws      <<<B_ * P_, 128>>>(s_j, Ws_w, Ws_b);
    k_uh_score<<<B_ * Q_, 256, SMEM_FUSED>>>(exp_tokens, exp_mask, v_w);
    k_softmax <<<B_ * P_, 256>>>();
    k_out     <<<B_ * Q_, 256, KO_SMEM>>>(exp_tokens, req_mask, out);
}

// round 12
// speedup vs baseline: 2.9514x; 1.0494x over previous
#include <cuda_runtime.h>
#include <cuda_bf16.h>
#include <cuda_fp16.h>
#include <cstdint>
#include <cstddef>

#define B_ 8
#define Q_ 32
#define T_ 128   // LE
#define D_ 512
#define P_ 32
#define A_ 128

// Scratch: ws (128KB), e/attn (4MB, layout [b][p][q][t]), Uw fp16 (160KB)
__device__ float g_ws[B_ * P_ * A_];
__device__ float g_e[(size_t)B_ * P_ * Q_ * T_];
// Uw as fp16, pre-padded 80B rows: [chunk 16][a 128][40 u16 (32 data + 8 pad)]
__device__ __align__(16) uint16_t g_uwh[16 * 128 * 40];

// ---------------- generic helpers ----------------
__device__ __forceinline__ float fast_tanh(float x) {
    float y; asm("tanh.approx.f32 %0, %1;" : "=f"(y) : "f"(x)); return y;
}
__device__ __forceinline__ uint32_t smem_u32(const void* p) {
    uint32_t a;
    asm("{ .reg .u64 t; cvta.to.shared.u64 t, %1; cvt.u32.u64 %0, t; }" : "=r"(a) : "l"(p));
    return a;
}
// f32 pair -> fp16x2 (rn)
__device__ __forceinline__ uint32_t cvt_f16x2(float x0, float x1) {
    __half2 h = __floats2half2_rn(x0, x1);
    return *reinterpret_cast<uint32_t*>(&h);
}
// split f32 pair -> fp16x2 hi + fp16x2 lo (hi+lo reconstructs to ~2^-22)
__device__ __forceinline__ void cvt_split_f16(float x0, float x1, uint32_t& h2, uint32_t& l2) {
    __half2 h = __floats2half2_rn(x0, x1);
    float2 hf = __half22float2(h);
    __half2 l = __floats2half2_rn(x0 - hf.x, x1 - hf.y);
    h2 = *reinterpret_cast<uint32_t*>(&h);
    l2 = *reinterpret_cast<uint32_t*>(&l);
}
__device__ __forceinline__ void ldmx4(uint32_t* r, uint32_t addr) {
    asm volatile("ldmatrix.sync.aligned.m8n8.x4.shared.b16 {%0,%1,%2,%3}, [%4];"
                 : "=r"(r[0]), "=r"(r[1]), "=r"(r[2]), "=r"(r[3]) : "r"(addr));
}
__device__ __forceinline__ void ldmx4t(uint32_t* r, uint32_t addr) {
    asm volatile("ldmatrix.sync.aligned.m8n8.x4.trans.shared.b16 {%0,%1,%2,%3}, [%4];"
                 : "=r"(r[0]), "=r"(r[1]), "=r"(r[2]), "=r"(r[3]) : "r"(addr));
}
__device__ __forceinline__ void mma_f16(float* d, const uint32_t* a, const uint32_t* b) {
    asm volatile("mma.sync.aligned.m16n8k16.row.col.f32.f16.f16.f32 "
                 "{%0,%1,%2,%3}, {%4,%5,%6,%7}, {%8,%9}, {%0,%1,%2,%3};"
                 : "+f"(d[0]), "+f"(d[1]), "+f"(d[2]), "+f"(d[3])
                 : "r"(a[0]), "r"(a[1]), "r"(a[2]), "r"(a[3]), "r"(b[0]), "r"(b[1]));
}

// ---------------- kernel 0: Uw -> fp16, padded layout ----------------
__global__ void k_prep(const float* __restrict__ Uw) {
    int a = blockIdx.x;          // 0..127
    int t = threadIdx.x;         // 0..127
    int k0 = t * 4;
    float4 v = *(const float4*)(Uw + (size_t)a * D_ + k0);
    int c = k0 >> 5, w = k0 & 31;
    uint32_t u0 = cvt_f16x2(v.x, v.y);
    uint32_t u1 = cvt_f16x2(v.z, v.w);
    char* dh = (char*)g_uwh + (size_t)(c * 128 + a) * 80 + w * 2;
    *(uint32_t*)dh = u0; *(uint32_t*)(dh + 4) = u1;
}

// ---------------- kernel 1: ws[b,p,a] = s_j[b,p,:] . Ws_w[a,:] + Ws_b[a] ----------------
__global__ void k_ws(const float* __restrict__ s_j,
                     const float* __restrict__ Ws_w,
                     const float* __restrict__ Ws_b) {
    __shared__ float srow[D_];
    int bp = blockIdx.x;
    int a  = threadIdx.x;
    ((float4*)srow)[a] = ((const float4*)(s_j + (size_t)bp * D_))[a];
    __syncthreads();
    const float* w = Ws_w + (size_t)a * D_;
    float acc = 0.f;
#pragma unroll 8
    for (int d = 0; d < D_; d++) acc = fmaf(srow[d], w[d], acc);
    g_ws[bp * A_ + a] = acc + Ws_b[a];
}

// ---------------- fused: HMMA uh GEMM (fp16 2-term) + compacted scores, per (b,q) --------
// dyn smem layout (bytes):
//   phase1: A_h [128][40 f16] @0 (10240) | A_l @10240 | B_h @20480 (10240)
//   phase2: uh_s float[128][130]  @0 (66560)   (overlays phase-1 tiles)
//   66560 : ws_t float[128][32] ([a][p]) 16KB
//   82944 : v_s   float[128]
//   83456 : mask_s int[128]
//   83968 : act_s int[128]
//   84480 : nact_s int
#define SMEM_FUSED 84608
#define OFF_AH 0
#define OFF_AL 10240
#define OFF_BH 20480
#define UH_STRIDE 130
#define OFF_WS 66560
#define OFF_V  82944
#define OFF_MK 83456
#define OFF_ACT 83968
#define OFF_NACT 84480

__global__ __launch_bounds__(256, 2) void k_uh_score(const float* __restrict__ tok,
                                                     const int* __restrict__ exp_mask,
                                                     const float* __restrict__ v_w) {
    extern __shared__ char smem[];
    uint32_t sb = smem_u32(smem);
    float* uh_s = (float*)smem;
    float* ws_t = (float*)(smem + OFF_WS);
    float* v_s  = (float*)(smem + OFF_V);
    int*   mask_s = (int*)(smem + OFF_MK);
    int*   act_s  = (int*)(smem + OFF_ACT);
    int*   nact_s = (int*)(smem + OFF_NACT);
    uint32_t* sBH = (uint32_t*)(smem + OFF_BH);

    int tid = threadIdx.x;
    int wid = tid >> 5, lane = tid & 31;
    int bq = blockIdx.x;
    int b = bq >> 5, q = bq & 31;
    int m0 = bq * 128;

    // preload ws (transposed), v, mask
#pragma unroll
    for (int s = 0; s < 16; s++) {
        int it = s * 256 + tid;          // p*128 + a
        int pp = it >> 7, aa = it & 127;
        ws_t[aa * 32 + pp] = g_ws[b * (P_ * A_) + it];
    }
    if (tid < 128) {
        v_s[tid] = v_w[tid];
        mask_s[tid] = exp_mask[(b * Q_ + q) * T_ + tid];
    }

    // ---- phase 1: GEMM uh[t][a] = sum_k tok[t,k] * Uw[a,k] ----
    int wm = wid & 3;        // m group: 32 rows
    int wn = wid >> 2;       // n group: 64 cols
    uint32_t a_lane = (uint32_t)((wm * 32 + (lane & 15)) * 80 + (lane >> 4) * 16);
    uint32_t b_row  = (uint32_t)(wn * 64 + (lane & 7) + ((lane >> 4) & 1) * 8);
    uint32_t b_lane = b_row * 80 + ((lane >> 3) & 1) * 16;

    // conversion mapping: r = tid>>1 (row 0..127), h = tid&1 (k half of 32)
    int cr = tid >> 1, ch = tid & 1;
    uint32_t cdst = (uint32_t)(cr * 80 + ch * 32);

    float acc[16][4];
#pragma unroll
    for (int i = 0; i < 16; i++)
#pragma unroll
        for (int j = 0; j < 4; j++) acc[i][j] = 0.f;

    const float* srcA0 = tok + (size_t)(m0 + cr) * D_ + ch * 16;
    const uint32_t* uwh32 = (const uint32_t*)g_uwh;

    // prime chunk-0 A prefetch
    float4 pa[4];
#pragma unroll
    for (int j = 0; j < 4; j++) pa[j] = *(const float4*)(srcA0 + j * 4);

#pragma unroll 1
    for (int c = 0; c < 16; c++) {
        // convert prefetched A regs -> smem hi/lo tiles
#pragma unroll
        for (int j4 = 0; j4 < 4; j4++) {
            uint32_t h2, l2;
            uint32_t bo = cdst + j4 * 8;
            cvt_split_f16(pa[j4].x, pa[j4].y, h2, l2);
            *(uint32_t*)(smem + OFF_AH + bo) = h2;
            *(uint32_t*)(smem + OFF_AL + bo) = l2;
            cvt_split_f16(pa[j4].z, pa[j4].w, h2, l2);
            *(uint32_t*)(smem + OFF_AH + bo + 4) = h2;
            *(uint32_t*)(smem + OFF_AL + bo + 4) = l2;
        }
        // copy B tile (pre-converted fp16, L2-hot)
        {
            const uint32_t* srcH = uwh32 + c * 2560 + tid;
#pragma unroll
            for (int j = 0; j < 10; j++) sBH[j * 256 + tid] = srcH[j * 256];
        }
        // prefetch next A chunk (overlaps with MMA below)
        if (c < 15) {
            const float* nsrc = srcA0 + (c + 1) * 32;
#pragma unroll
            for (int j = 0; j < 4; j++) pa[j] = *(const float4*)(nsrc + j * 4);
        }
        __syncthreads();

#pragma unroll
        for (int ks = 0; ks < 2; ks++) {
            uint32_t koff = (uint32_t)(ks * 32);
            uint32_t ah[2][4], al[2][4];
#pragma unroll
            for (int mt = 0; mt < 2; mt++) {
                ldmx4(ah[mt], sb + OFF_AH + a_lane + mt * 1280 + koff);
                ldmx4(al[mt], sb + OFF_AL + a_lane + mt * 1280 + koff);
            }
#pragma unroll
            for (int ng = 0; ng < 4; ng++) {
                uint32_t bh[4];
                ldmx4(bh, sb + OFF_BH + b_lane + ng * 1280 + koff);
#pragma unroll
                for (int mt = 0; mt < 2; mt++)
#pragma unroll
                    for (int nt = 0; nt < 2; nt++) {
                        float* d = acc[mt * 8 + ng * 2 + nt];
                        mma_f16(d, ah[mt], bh + nt * 2);   // hi * B
                        mma_f16(d, al[mt], bh + nt * 2);   // lo * B
                    }
            }
        }
        __syncthreads();
    }

    // ---- spill uh fragments to smem (overlays tile buffers) ----
    {
        int r0 = wm * 32 + (lane >> 2);
        int c0 = wn * 64 + (lane & 3) * 2;
#pragma unroll
        for (int mt = 0; mt < 2; mt++)
#pragma unroll
            for (int j = 0; j < 8; j++) {
                float* d = acc[mt * 8 + j];
                int row = r0 + mt * 16;
                int col = c0 + j * 8;
                *(float2*)(uh_s + row * UH_STRIDE + col)       = make_float2(d[0], d[1]);
                *(float2*)(uh_s + (row + 8) * UH_STRIDE + col) = make_float2(d[2], d[3]);
            }
    }
    __syncthreads();

    // ---- compact active t list (warp 0) ----
    if (wid == 0) {
        int base = 0;
#pragma unroll
        for (int g = 0; g < 4; g++) {
            int m = (mask_s[g * 32 + lane] != 0);
            uint32_t bal = __ballot_sync(0xffffffffu, m);
            int pos = __popc(bal & ((1u << lane) - 1));
            if (m) act_s[base + pos] = g * 32 + lane;
            base += __popc(bal);
        }
        for (int s2 = base + lane; s2 < 128; s2 += 32) act_s[s2] = 0;
        if (lane == 0) *nact_s = base;
    }
    __syncthreads();

    int nact = *nact_s;

    // ---- dead-row writes: e = -1e9 where mask==0 ----
    {
        int t = tid & 127, ph = tid >> 7;    // ph 0/1 covers p halves
        if (mask_s[t] == 0) {
            float* eb = g_e + ((size_t)(b * P_ + ph * 16) * Q_ + q) * T_ + t;
#pragma unroll
            for (int p = 0; p < 16; p++) eb[(size_t)p * (Q_ * T_)] = -1e9f;
        }
    }

    // ---- phase 2: scores only for active t (compacted) ----
    int sub = wid & 3, phalf = wid >> 2;
    int slot = sub * 32 + lane;
    if (slot < nact) {
        int t = act_s[slot];
        const float* urow = uh_s + t * UH_STRIDE;
        const float* wbase = ws_t + phalf * 16;
        float accp[16];
#pragma unroll
        for (int p = 0; p < 16; p++) accp[p] = 0.f;

#pragma unroll 4
        for (int a = 0; a < 128; a++) {
            float u  = urow[a];
            float va = v_s[a];
            const float* wr = wbase + a * 32;
#pragma unroll
            for (int p = 0; p < 16; p++)
                accp[p] = fmaf(va, fast_tanh(u + wr[p]), accp[p]);
        }

        float* eb = g_e + ((size_t)(b * P_ + phalf * 16) * Q_ + q) * T_ + t;
#pragma unroll
        for (int p = 0; p < 16; p++)
            eb[(size_t)p * (Q_ * T_)] = accp[p];
    }
}

// ---------------- softmax over 4096 contiguous elems per (b,p), in place ----------------
__global__ __launch_bounds__(256) void k_softmax() {
    __shared__ float red[8];
    int bp = blockIdx.x;
    int tid = threadIdx.x;
    int lane = tid & 31, w = tid >> 5;
    float* e = g_e + (size_t)bp * (Q_ * T_);

    float buf[16];
    float4* ep = (float4*)(e + tid * 16);
#pragma unroll
    for (int j = 0; j < 4; j++) {
        float4 v = ep[j];
        buf[4 * j + 0] = v.x; buf[4 * j + 1] = v.y;
        buf[4 * j + 2] = v.z; buf[4 * j + 3] = v.w;
    }
    float mx = -3.4e38f;
#pragma unroll
    for (int j = 0; j < 16; j++) mx = fmaxf(mx, buf[j]);
#pragma unroll
    for (int o = 16; o > 0; o >>= 1) mx = fmaxf(mx, __shfl_xor_sync(0xffffffffu, mx, o));
    if (lane == 0) red[w] = mx;
    __syncthreads();
    mx = red[0];
#pragma unroll
    for (int i = 1; i < 8; i++) mx = fmaxf(mx, red[i]);

    float sm = 0.f;
#pragma unroll
    for (int j = 0; j < 16; j++) {
        float ex = __expf(buf[j] - mx);
        buf[j] = ex;
        sm += ex;
    }
#pragma unroll
    for (int o = 16; o > 0; o >>= 1) sm += __shfl_xor_sync(0xffffffffu, sm, o);
    __syncthreads();
    if (lane == 0) red[w] = sm;
    __syncthreads();
    sm = 0.f;
#pragma unroll
    for (int i = 0; i < 8; i++) sm += red[i];
    float inv = 1.0f / sm;

#pragma unroll
    for (int j = 0; j < 4; j++)
        ep[j] = make_float4(buf[4 * j + 0] * inv, buf[4 * j + 1] * inv,
                            buf[4 * j + 2] * inv, buf[4 * j + 3] * inv);
}

// ---------------- k_out (HMMA fp16, K compacted to active t) ----------------
// dyn smem: attn_h @0 (32*272=8704) | attn_l @8704 | tok_h @17408 (16*1040=16640)
//           act @34048 (512) | nact @34560
#define KO_AH 0
#define KO_AL 8704
#define KO_TH 17408
#define KO_ACT 34048
#define KO_NACT 34560
#define KO_SMEM 34688

__global__ __launch_bounds__(256, 2) void k_out(const float* __restrict__ tok,
                                                const int* __restrict__ exp_mask,
                                                const int* __restrict__ req_mask,
                                                float* __restrict__ out) {
    extern __shared__ char smem[];
    uint32_t sb = smem_u32(smem);
    int*   act_s  = (int*)(smem + KO_ACT);
    int*   nact_s = (int*)(smem + KO_NACT);
    int bq = blockIdx.x;
    int b = bq >> 5, q = bq & 31;
    int tid = threadIdx.x;
    int wid = tid >> 5, lane = tid & 31;

    // ---- compact active t list (warp 0) ----
    if (wid == 0) {
        int base = 0;
        const int* mk = exp_mask + (b * Q_ + q) * T_;
#pragma unroll
        for (int g = 0; g < 4; g++) {
            int m = (mk[g * 32 + lane] != 0);
            uint32_t bal = __ballot_sync(0xffffffffu, m);
            int pos = __popc(bal & ((1u << lane) - 1));
            if (m) act_s[base + pos] = g * 32 + lane;
            base += __popc(bal);
        }
        for (int s2 = base + lane; s2 < 128; s2 += 32) act_s[s2] = 0;
        if (lane == 0) *nact_s = base;
    }
    __syncthreads();
    int nact = *nact_s;
    int nch = (nact + 15) >> 4;   // K chunks of 16

    // ---- gather + convert attn (32 p x compacted t), pad with zeros ----
#pragma unroll
    for (int s = 0; s < 4; s++) {
        int idx = s * 256 + tid;          // 0..1023
        int r  = idx >> 5;                // p row 0..31
        int jj = (idx & 31) * 4;          // 4 consecutive compacted columns
        const float* erow = g_e + ((size_t)(b * P_ + r) * Q_ + q) * T_;
        float v0 = (jj + 0 < nact) ? erow[act_s[jj + 0]] : 0.f;
        float v1 = (jj + 1 < nact) ? erow[act_s[jj + 1]] : 0.f;
        float v2 = (jj + 2 < nact) ? erow[act_s[jj + 2]] : 0.f;
        float v3 = (jj + 3 < nact) ? erow[act_s[jj + 3]] : 0.f;
        uint32_t h0, l0, h1, l1;
        cvt_split_f16(v0, v1, h0, l0);
        cvt_split_f16(v2, v3, h1, l1);
        uint32_t bo = (uint32_t)(r * 272 + jj * 2);
        *(uint32_t*)(smem + KO_AH + bo)     = h0;
        *(uint32_t*)(smem + KO_AH + bo + 4) = h1;
        *(uint32_t*)(smem + KO_AL + bo)     = l0;
        *(uint32_t*)(smem + KO_AL + bo + 4) = l1;
    }

    int wm = wid & 1;        // m tile: 16 p rows
    int wn = wid >> 1;       // n group: 128 d cols
    uint32_t a_lane = (uint32_t)((wm * 16 + (lane & 15)) * 272 + (lane >> 4) * 16);
    // trans-ldmatrix lane mapping for tok B tiles
    int bmat = lane >> 3;
    uint32_t bt_row = (uint32_t)((bmat & 1) * 8 + (lane & 7));
    uint32_t bt_col = (uint32_t)((bmat >> 1) * 8);

    // conversion mapping: r = tid&15 (compacted t row), seg = tid>>4 (32 d cols)
    int cvr = tid & 15, cvs = tid >> 4;

    float acc[16][4];
#pragma unroll
    for (int i = 0; i < 16; i++)
#pragma unroll
        for (int j = 0; j < 4; j++) acc[i][j] = 0.f;

    const float* tb = tok + (size_t)bq * T_ * D_;

#pragma unroll 1
    for (int c = 0; c < nch; c++) {
        // gather + convert tok chunk (16 active t rows x 512 d), fp16
        int slot = c * 16 + cvr;
        int trow = (slot < nact) ? act_s[slot] : 0;
        const float* src = tb + (size_t)trow * D_ + cvs * 32;
        uint32_t bo0 = (uint32_t)(cvr * 1040 + cvs * 64);
#pragma unroll
        for (int j4 = 0; j4 < 8; j4++) {
            float4 v = *(const float4*)(src + j4 * 4);
            uint32_t bo = bo0 + j4 * 8;
            *(uint32_t*)(smem + KO_TH + bo)     = cvt_f16x2(v.x, v.y);
            *(uint32_t*)(smem + KO_TH + bo + 4) = cvt_f16x2(v.z, v.w);
        }
        __syncthreads();

        uint32_t ah[4], al[4];
        ldmx4(ah, sb + KO_AH + a_lane + c * 32);
        ldmx4(al, sb + KO_AL + a_lane + c * 32);
#pragma unroll
        for (int ng = 0; ng < 8; ng++) {
            uint32_t n0 = (uint32_t)(wn * 128 + ng * 16);
            uint32_t baddr = bt_row * 1040 + (n0 + bt_col) * 2;
            uint32_t bh[4];
            ldmx4t(bh, sb + KO_TH + baddr);
#pragma unroll
            for (int nt = 0; nt < 2; nt++) {
                float* d = acc[ng * 2 + nt];
                mma_f16(d, ah, bh + nt * 2);
                mma_f16(d, al, bh + nt * 2);
            }
        }
        __syncthreads();
    }

    // ---- epilogue ----
    int r0 = wm * 16 + (lane >> 2);
    int c0 = wn * 128 + (lane & 3) * 2;
    float rm0 = (float)req_mask[b * P_ + r0];
    float rm1 = (float)req_mask[b * P_ + r0 + 8];
    float* ob = out + (size_t)bq * P_ * D_;
#pragma unroll
    for (int i = 0; i < 16; i++) {
        float* d = acc[i];
        int col = c0 + (i >> 1) * 16 + (i & 1) * 8;
        *(float2*)(ob + (size_t)r0 * D_ + col)       = make_float2(d[0] * rm0, d[1] * rm0);
        *(float2*)(ob + (size_t)(r0 + 8) * D_ + col) = make_float2(d[2] * rm1, d[3] * rm1);
    }
}

// ---------------- launch ----------------
extern "C" void kernel_launch(void* const* d_in, const int* in_sizes, int n_in,
                              void* d_out, int out_size) {
    const float* exp_tokens = (const float*)d_in[0];  // (B,Q,LE,D) f32
    const int*   exp_mask   = (const int*)  d_in[1];  // (B,Q,LE) i32
    const float* s_j        = (const float*)d_in[2];  // (B,P,D) f32
    const int*   req_mask   = (const int*)  d_in[3];  // (B,P) i32
    const float* Ws_w       = (const float*)d_in[4];  // (A,D)
    const float* Ws_b       = (const float*)d_in[5];  // (A,)
    const float* U_w        = (const float*)d_in[6];  // (A,D)
    const float* v_w        = (const float*)d_in[7];  // (1,A)
    float* out = (float*)d_out;                       // (B,Q,P,D) f32

    cudaFuncSetAttribute(k_uh_score, cudaFuncAttributeMaxDynamicSharedMemorySize, SMEM_FUSED);
    cudaFuncSetAttribute(k_out, cudaFuncAttributeMaxDynamicSharedMemorySize, KO_SMEM);

    k_prep    <<<128, 128>>>(U_w);
    k_ws      <<<B_ * P_, 128>>>(s_j, Ws_w, Ws_b);
    k_uh_score<<<B_ * Q_, 256, SMEM_FUSED>>>(exp_tokens, exp_mask, v_w);
    k_softmax <<<B_ * P_, 256>>>();
    k_out     <<<B_ * Q_, 256, KO_SMEM>>>(exp_tokens, exp_mask, req_mask, out);
}